// round 1
// baseline (speedup 1.0000x reference)
#include <cuda_runtime.h>
#include <cuda_bf16.h>
#include <math.h>

// Problem constants
#define BSZ   512
#define TT    64          // used timesteps (T_TOTAL-1)
#define TTOT  65
#define FEAT  512
#define HID   1000
#define GAPS  16
#define EPSV  1e-5f

// ---------------- scratch (device globals; allocation-free) ----------------
// time-major layouts: [T][B][F] so per-step slices are contiguous.
__device__ float g_prex[TT * BSZ * FEAT];     // x@W_ih^T + b_ih
__device__ float g_hs  [TT * BSZ * FEAT];     // hidden states
__device__ float g_z1  [TT * BSZ * HID];
__device__ float g_z2  [TT * BSZ * HID];
__device__ float g_y   [TT * BSZ * FEAT];
__device__ float g_xall[GAPS * BSZ * FEAT];   // decoded x per gap
__device__ float g_tmp [BSZ * FEAT];          // x_hat@W_ih^T + b_ih (decode)
__device__ float g_hA  [BSZ * FEAT];
__device__ float g_hB  [BSZ * FEAT];
__device__ float g_z1d [BSZ * HID];
__device__ float g_z2d [BSZ * HID];
__device__ double g_loss[2];

// ---------------- generic tiled GEMM:  C = ep(A @ W^T + bias) ---------------
// A: rows addressed as  off(m) = (m/rowDiv)*rowS1 + (m%rowDiv)*rowS2
// W: (N,K) row-major.  C/Add: row stride N.
// MODE 0: C = acc + bias
// MODE 1: C = tanh(acc + bias + Add)
// MODE 2: C = (acc + bias - rm) * (gam * rsqrt(rv+eps)) + beta
template<int MODE, int BM, int BN, int TM, int TN>
__global__ void __launch_bounds__(256) gemm_k(
    const float* __restrict__ A, const float* __restrict__ W,
    const float* __restrict__ bias, const float* __restrict__ Add,
    const float* __restrict__ gam, const float* __restrict__ rm,
    const float* __restrict__ rv,  const float* __restrict__ bet,
    float* __restrict__ C, int M, int N, int K,
    int rowDiv, int rowS1, int rowS2)
{
    constexpr int BK = 16;
    constexpr int TX = BN / TN;
    constexpr int TY = BM / TM;
    static_assert(TX * TY == 256, "thread count");

    __shared__ float As[BK][BM + 4];
    __shared__ float Bs[BK][BN + 4];

    const int tid = threadIdx.x;
    const int tx  = tid % TX;
    const int ty  = tid / TX;
    const int bm0 = blockIdx.y * BM;
    const int bn0 = blockIdx.x * BN;

    float acc[TM][TN];
#pragma unroll
    for (int i = 0; i < TM; i++)
#pragma unroll
        for (int j = 0; j < TN; j++) acc[i][j] = 0.f;

    constexpr int A4 = BM * BK / 4;   // float4 loads per A tile
    constexpr int B4 = BN * BK / 4;

    for (int k0 = 0; k0 < K; k0 += BK) {
        // ---- load A tile (transposed into As[k][m]) ----
#pragma unroll
        for (int idx = tid; idx < A4; idx += 256) {
            int arow = idx >> 2;
            int ak4  = idx & 3;
            int m    = bm0 + arow;
            int kk   = k0 + ak4 * 4;
            float4 v = make_float4(0.f, 0.f, 0.f, 0.f);
            if (m < M && kk + 3 < K) {
                long off = (long)(m / rowDiv) * rowS1 + (long)(m % rowDiv) * rowS2;
                v = *reinterpret_cast<const float4*>(A + off + kk);
            }
            As[ak4 * 4 + 0][arow] = v.x;
            As[ak4 * 4 + 1][arow] = v.y;
            As[ak4 * 4 + 2][arow] = v.z;
            As[ak4 * 4 + 3][arow] = v.w;
        }
        // ---- load W tile ----
#pragma unroll
        for (int idx = tid; idx < B4; idx += 256) {
            int brow = idx >> 2;
            int bk4  = idx & 3;
            int n    = bn0 + brow;
            int kk   = k0 + bk4 * 4;
            float4 v = make_float4(0.f, 0.f, 0.f, 0.f);
            if (n < N && kk + 3 < K)
                v = *reinterpret_cast<const float4*>(W + (long)n * K + kk);
            Bs[bk4 * 4 + 0][brow] = v.x;
            Bs[bk4 * 4 + 1][brow] = v.y;
            Bs[bk4 * 4 + 2][brow] = v.z;
            Bs[bk4 * 4 + 3][brow] = v.w;
        }
        __syncthreads();

#pragma unroll
        for (int k = 0; k < BK; k++) {
            float a[TM], b[TN];
#pragma unroll
            for (int i = 0; i < TM; i++) a[i] = As[k][ty * TM + i];
#pragma unroll
            for (int j = 0; j < TN; j++) b[j] = Bs[k][tx * TN + j];
#pragma unroll
            for (int i = 0; i < TM; i++)
#pragma unroll
                for (int j = 0; j < TN; j++)
                    acc[i][j] = fmaf(a[i], b[j], acc[i][j]);
        }
        __syncthreads();
    }

    // ---- epilogue ----
    float pb[TN], prm[TN], psc[TN], pbe[TN];
#pragma unroll
    for (int j = 0; j < TN; j++) {
        int col = bn0 + tx * TN + j;
        int cc  = (col < N) ? col : 0;
        pb[j] = bias[cc];
        if (MODE == 2) {
            prm[j] = rm[cc];
            psc[j] = gam[cc] * rsqrtf(rv[cc] + EPSV);
            pbe[j] = bet[cc];
        }
    }
#pragma unroll
    for (int i = 0; i < TM; i++) {
        int row = bm0 + ty * TM + i;
        if (row >= M) continue;
#pragma unroll
        for (int j = 0; j < TN; j++) {
            int col = bn0 + tx * TN + j;
            if (col >= N) continue;
            float v = acc[i][j] + pb[j];
            if (MODE == 1) v = tanhf(v + Add[(long)row * N + col]);
            if (MODE == 2) v = (v - prm[j]) * psc[j] + pbe[j];
            C[(long)row * N + col] = v;
        }
    }
}

// first RNN step: h0 = 0, so h1 = tanh(prex[0] + b_hh)
__global__ void step0_k(const float* __restrict__ prex,
                        const float* __restrict__ b_hh,
                        float* __restrict__ hs)
{
    int idx = blockIdx.x * blockDim.x + threadIdx.x;   // BSZ*FEAT = 262144
    hs[idx] = tanhf(prex[idx] + b_hh[idx & (FEAT - 1)]);
}

__global__ void zero_k() { g_loss[0] = 0.0; g_loss[1] = 0.0; }

// loss1: sum over t in [0,63), b, f of (y[t,b,f] - x[b,t+1,f])^2
__global__ void loss1_k(const float* __restrict__ y, const float* __restrict__ x)
{
    __shared__ double sm[256];
    const int total = (TT - 1) * BSZ * FEAT;   // 16,515,072
    double s = 0.0;
    for (int idx = blockIdx.x * blockDim.x + threadIdx.x; idx < total;
         idx += gridDim.x * blockDim.x) {
        int f = idx & (FEAT - 1);
        int b = (idx >> 9) & (BSZ - 1);
        int t = idx >> 18;
        float d = y[idx] - x[(b * TTOT + t + 1) * FEAT + f];
        s += (double)d * (double)d;
    }
    sm[threadIdx.x] = s;
    __syncthreads();
    for (int o = 128; o > 0; o >>= 1) {
        if (threadIdx.x < o) sm[threadIdx.x] += sm[threadIdx.x + o];
        __syncthreads();
    }
    if (threadIdx.x == 0) atomicAdd(&g_loss[0], sm[0]);
}

// gather x_pred per-batch gap + loss2 accumulation
__global__ void gather_k(const float* __restrict__ xall, const int* __restrict__ tt,
                         const float* __restrict__ x, float* __restrict__ out)
{
    __shared__ double sm[256];
    int idx = blockIdx.x * blockDim.x + threadIdx.x;   // 262144 exactly
    int b = idx >> 9, f = idx & (FEAT - 1);
    int g = tt[b] - 1;
    float v = xall[(g * BSZ + b) * FEAT + f];
    out[idx] = v;
    float d = v - x[(b * TTOT + TTOT - 1) * FEAT + f];
    sm[threadIdx.x] = (double)d * (double)d;
    __syncthreads();
    for (int o = 128; o > 0; o >>= 1) {
        if (threadIdx.x < o) sm[threadIdx.x] += sm[threadIdx.x + o];
        __syncthreads();
    }
    if (threadIdx.x == 0) atomicAdd(&g_loss[1], sm[0]);
}

__global__ void fin_k(float* __restrict__ out)
{
    const double n1 = (double)(TT - 1) * BSZ * FEAT;
    const double n2 = (double)BSZ * FEAT;
    out[BSZ * FEAT] = (float)(g_loss[0] / (n1 * n1) + g_loss[1] / (n2 * n2));
}

// ---------------- host orchestration ----------------
template<int MODE, int BM, int BN, int TM, int TN>
static void rungemm(const float* A, const float* W, const float* bias,
                    const float* Add, const float* gam, const float* rm,
                    const float* rv, const float* bet, float* C,
                    int M, int N, int K, int rowDiv, int rowS1, int rowS2)
{
    dim3 grid((N + BN - 1) / BN, (M + BM - 1) / BM);
    gemm_k<MODE, BM, BN, TM, TN><<<grid, 256>>>(A, W, bias, Add, gam, rm, rv,
                                                bet, C, M, N, K,
                                                rowDiv, rowS1, rowS2);
}

extern "C" void kernel_launch(void* const* d_in, const int* in_sizes, int n_in,
                              void* d_out, int out_size)
{
    const float* x    = (const float*)d_in[0];
    const int*   tt   = (const int*)  d_in[1];
    const float* W_ih = (const float*)d_in[2];
    const float* W_hh = (const float*)d_in[3];
    const float* b_ih = (const float*)d_in[4];
    const float* b_hh = (const float*)d_in[5];
    const float* W1   = (const float*)d_in[6];
    const float* b1   = (const float*)d_in[7];
    const float* g1   = (const float*)d_in[8];
    const float* be1  = (const float*)d_in[9];
    const float* rm1  = (const float*)d_in[10];
    const float* rv1  = (const float*)d_in[11];
    const float* W2   = (const float*)d_in[12];
    const float* b2   = (const float*)d_in[13];
    const float* g2   = (const float*)d_in[14];
    const float* be2  = (const float*)d_in[15];
    const float* rm2  = (const float*)d_in[16];
    const float* rv2  = (const float*)d_in[17];
    const float* W3   = (const float*)d_in[18];
    const float* b3   = (const float*)d_in[19];
    const float* g3   = (const float*)d_in[20];
    const float* be3  = (const float*)d_in[21];
    const float* rm3  = (const float*)d_in[22];
    const float* rv3  = (const float*)d_in[23];
    float* out = (float*)d_out;

    float *prex, *hs, *z1, *z2, *y, *xall, *tmp, *hA, *hB, *z1d, *z2d;
    cudaGetSymbolAddress((void**)&prex, g_prex);
    cudaGetSymbolAddress((void**)&hs,   g_hs);
    cudaGetSymbolAddress((void**)&z1,   g_z1);
    cudaGetSymbolAddress((void**)&z2,   g_z2);
    cudaGetSymbolAddress((void**)&y,    g_y);
    cudaGetSymbolAddress((void**)&xall, g_xall);
    cudaGetSymbolAddress((void**)&tmp,  g_tmp);
    cudaGetSymbolAddress((void**)&hA,   g_hA);
    cudaGetSymbolAddress((void**)&hB,   g_hB);
    cudaGetSymbolAddress((void**)&z1d,  g_z1d);
    cudaGetSymbolAddress((void**)&z2d,  g_z2d);

    const int BF  = BSZ * FEAT;
    const int BIGM = TT * BSZ;   // 32768
    const int NOROW = 1 << 30;   // "identity" row mapping

    zero_k<<<1, 1>>>();

    // 1. prex[t*B+b] = x[b,t,:] @ W_ih^T + b_ih   (one big GEMM, full chip)
    //    A row m: t = m/BSZ, b = m%BSZ -> offset t*FEAT + b*(TTOT*FEAT)
    rungemm<0, 128, 64, 8, 4>(x, W_ih, b_ih, nullptr, nullptr, nullptr, nullptr,
                              nullptr, prex, BIGM, FEAT, FEAT,
                              BSZ, FEAT, TTOT * FEAT);

    // 2. serial RNN scan (time-major, contiguous slabs)
    step0_k<<<BF / 256, 256>>>(prex, b_hh, hs);
    for (int s = 1; s < TT; s++) {
        rungemm<1, 64, 32, 4, 2>(hs + (s - 1) * BF, W_hh, b_hh, prex + s * BF,
                                 nullptr, nullptr, nullptr, nullptr,
                                 hs + s * BF, BSZ, FEAT, FEAT,
                                 NOROW, 0, FEAT);
    }

    // 3. autoencoder over all 32768 rows (dominant cost)
    rungemm<2, 128, 64, 8, 4>(hs, W1, b1, nullptr, g1, rm1, rv1, be1,
                              z1, BIGM, HID, FEAT, NOROW, 0, FEAT);
    rungemm<2, 128, 64, 8, 4>(z1, W2, b2, nullptr, g2, rm2, rv2, be2,
                              z2, BIGM, HID, HID, NOROW, 0, HID);
    rungemm<2, 128, 64, 8, 4>(z2, W3, b3, nullptr, g3, rm3, rv3, be3,
                              y, BIGM, FEAT, HID, NOROW, 0, HID);

    // 4. loss1
    loss1_k<<<2048, 256>>>(y, x);

    // 5. decode: 16 serial iterations
    const float* hprev = hs + (TT - 1) * BF;   // h[:, -1]
    const float* xprev = y  + (TT - 1) * BF;   // y[:, -1]
    for (int g = 0; g < GAPS; g++) {
        float* hcur = (g & 1) ? hB : hA;
        float* xcur = xall + g * BF;
        rungemm<0, 64, 32, 4, 2>(xprev, W_ih, b_ih, nullptr, nullptr, nullptr,
                                 nullptr, nullptr, tmp, BSZ, FEAT, FEAT,
                                 NOROW, 0, FEAT);
        rungemm<1, 64, 32, 4, 2>(hprev, W_hh, b_hh, tmp, nullptr, nullptr,
                                 nullptr, nullptr, hcur, BSZ, FEAT, FEAT,
                                 NOROW, 0, FEAT);
        rungemm<2, 64, 32, 4, 2>(hcur, W1, b1, nullptr, g1, rm1, rv1, be1,
                                 z1d, BSZ, HID, FEAT, NOROW, 0, FEAT);
        rungemm<2, 64, 32, 4, 2>(z1d, W2, b2, nullptr, g2, rm2, rv2, be2,
                                 z2d, BSZ, HID, HID, NOROW, 0, HID);
        rungemm<2, 64, 32, 4, 2>(z2d, W3, b3, nullptr, g3, rm3, rv3, be3,
                                 xcur, BSZ, FEAT, HID, NOROW, 0, HID);
        hprev = hcur;
        xprev = xcur;
    }

    // 6. gather x_pred + loss2, then finalize scalar loss
    gather_k<<<BF / 256, 256>>>(xall, tt, x, out);
    if (out_size > BSZ * FEAT) fin_k<<<1, 1>>>(out);
}

// round 4
// speedup vs baseline: 1.2782x; 1.2782x over previous
#include <cuda_runtime.h>
#include <cuda_bf16.h>
#include <math.h>

// Problem constants
#define BSZ   512
#define TT    64          // used timesteps (T_TOTAL-1)
#define TTOT  65
#define FEAT  512
#define HID   1000
#define GAPS  16
#define EPSV  1e-5f
#define SCAN_GRID 128     // persistent scan CTAs (<= 148 SMs, 1 CTA/SM)

// ---------------- scratch (device globals; allocation-free) ----------------
__device__ float g_prex[TT * BSZ * FEAT];     // x@W_ih^T + b_ih   (time-major)
__device__ float g_hs  [TT * BSZ * FEAT];     // hidden states     (time-major)
__device__ float g_z1  [TT * BSZ * HID];
__device__ float g_z2  [TT * BSZ * HID];
__device__ float g_y   [TT * BSZ * FEAT];
__device__ float g_xall[GAPS * BSZ * FEAT];
__device__ float g_hA  [BSZ * FEAT];
__device__ float g_hB  [BSZ * FEAT];
__device__ float g_z1d [BSZ * HID];
__device__ float g_z2d [BSZ * HID];
__device__ double g_loss[2];
__device__ int    g_bar;                      // software grid barrier counter

// ======================= persistent RNN scan kernel =========================
// 128 CTAs: blockIdx -> (mb = bid>>3 [16 tiles of 32 rows], nb = bid&7 [8 tiles
// of 64 cols]). Each CTA keeps W_hh[n0:n0+64, :] TRANSPOSED in dynamic smem
// (Wt[k][n], 512x68 pad) for all 64 steps. Grid barrier between steps.
__global__ void __launch_bounds__(256) scan_k(const float* __restrict__ prex,
                                              const float* __restrict__ W_hh,
                                              const float* __restrict__ b_hh,
                                              float* __restrict__ hs)
{
    extern __shared__ float Wt[];             // [512][68]
    __shared__ float As[32][34];              // A chunk, As[k][m]

    const int tid = threadIdx.x;
    const int nb  = blockIdx.x & 7;
    const int mb  = blockIdx.x >> 3;
    const int n0  = nb * 64;
    const int m0  = mb * 32;
    const int tx  = tid & 15;                 // 16 col groups (4 cols each)
    const int ty  = tid >> 4;                 // 16 row groups (2 rows each)

    // load W slice transposed: Wt[k][n] = W_hh[(n0+n)*512 + k]  (coalesced in k)
    for (int idx = tid; idx < 64 * 512; idx += 256) {
        int n = idx >> 9, k = idx & 511;
        Wt[k * 68 + n] = W_hh[(n0 + n) * FEAT + k];
    }
    float bh[4];
#pragma unroll
    for (int j = 0; j < 4; j++) bh[j] = b_hh[n0 + tx * 4 + j];
    __syncthreads();

    const int lrow = tid >> 3;                // A-chunk loader row (0..31)
    const int lkc  = (tid & 7) * 4;           // A-chunk loader k offset

    int tgt = 0;
    for (int s = 0; s < TT; s++) {
        float acc[2][4];
#pragma unroll
        for (int i = 0; i < 2; i++)
#pragma unroll
            for (int j = 0; j < 4; j++) acc[i][j] = 0.f;

        if (s > 0) {
            const float* hp = hs + (size_t)(s - 1) * BSZ * FEAT;
            // prefetch first chunk
            float4 v = *reinterpret_cast<const float4*>(
                hp + (m0 + lrow) * FEAT + lkc);
            for (int k0 = 0; k0 < FEAT; k0 += 32) {
                __syncthreads();
                As[lkc + 0][lrow] = v.x;
                As[lkc + 1][lrow] = v.y;
                As[lkc + 2][lrow] = v.z;
                As[lkc + 3][lrow] = v.w;
                __syncthreads();
                if (k0 + 32 < FEAT)
                    v = *reinterpret_cast<const float4*>(
                        hp + (m0 + lrow) * FEAT + k0 + 32 + lkc);
#pragma unroll
                for (int k = 0; k < 32; k++) {
                    float2 a = *reinterpret_cast<const float2*>(&As[k][ty * 2]);
                    float4 b = *reinterpret_cast<const float4*>(
                        &Wt[(k0 + k) * 68 + tx * 4]);
                    acc[0][0] = fmaf(a.x, b.x, acc[0][0]);
                    acc[0][1] = fmaf(a.x, b.y, acc[0][1]);
                    acc[0][2] = fmaf(a.x, b.z, acc[0][2]);
                    acc[0][3] = fmaf(a.x, b.w, acc[0][3]);
                    acc[1][0] = fmaf(a.y, b.x, acc[1][0]);
                    acc[1][1] = fmaf(a.y, b.y, acc[1][1]);
                    acc[1][2] = fmaf(a.y, b.z, acc[1][2]);
                    acc[1][3] = fmaf(a.y, b.w, acc[1][3]);
                }
            }
        }
        // epilogue: h_s = tanh(acc + prex_s + b_hh)
        const float* px = prex + (size_t)s * BSZ * FEAT;
        float*       ho = hs   + (size_t)s * BSZ * FEAT;
#pragma unroll
        for (int i = 0; i < 2; i++) {
            int m = m0 + ty * 2 + i;
#pragma unroll
            for (int j = 0; j < 4; j++) {
                int n = n0 + tx * 4 + j;
                ho[m * FEAT + n] = tanhf(acc[i][j] + px[m * FEAT + n] + bh[j]);
            }
        }
        // grid barrier: release (fence+atomic) then acquire (fence after spin)
        tgt += SCAN_GRID;
        __syncthreads();
        if (tid == 0) {
            __threadfence();
            atomicAdd(&g_bar, 1);
            while (*(volatile int*)&g_bar < tgt) __nanosleep(64);
            __threadfence();   // acquire: order peer-CTA hs writes before reads
        }
        __syncthreads();
    }
}

// ================== small GEMM (decode): 32x32 tile, BK=32 ==================
// MODE 0: C = acc + bias
// MODE 1: C = tanh(acc + bias + bias2)           (cell; DUAL=1 folds h@W_hh^T)
// MODE 2: C = (acc + bias - rm)*(gam*rsqrt(rv+eps)) + beta
template<int MODE, int DUAL>
__global__ void __launch_bounds__(256) sgemm_k(
    const float* __restrict__ A,  const float* __restrict__ W,  int K,
    const float* __restrict__ A2, const float* __restrict__ W2, int K2,
    const float* __restrict__ bias, const float* __restrict__ bias2,
    const float* __restrict__ gam, const float* __restrict__ rm,
    const float* __restrict__ rv,  const float* __restrict__ bet,
    float* __restrict__ C, int M, int N)
{
    __shared__ float As[32][34];
    __shared__ float Bs[32][34];
    const int tid = threadIdx.x;
    const int tx  = tid & 15;
    const int ty  = tid >> 4;
    const int m0  = blockIdx.y * 32;
    const int n0  = blockIdx.x * 32;
    const int lrow = tid >> 3;
    const int lkc  = (tid & 7) * 4;

    float acc[2][2] = {{0.f, 0.f}, {0.f, 0.f}};

#pragma unroll
    for (int pass = 0; pass < 1 + DUAL; pass++) {
        const float* Ap = pass ? A2 : A;
        const float* Wp = pass ? W2 : W;
        const int    Kp = pass ? K2 : K;
        for (int k0 = 0; k0 < Kp; k0 += 32) {
            __syncthreads();
            float4 va = make_float4(0.f, 0.f, 0.f, 0.f);
            if (k0 + lkc + 3 < Kp)
                va = *reinterpret_cast<const float4*>(
                    Ap + (size_t)(m0 + lrow) * Kp + k0 + lkc);
            As[lkc + 0][lrow] = va.x;
            As[lkc + 1][lrow] = va.y;
            As[lkc + 2][lrow] = va.z;
            As[lkc + 3][lrow] = va.w;
            float4 vb = make_float4(0.f, 0.f, 0.f, 0.f);
            if ((n0 + lrow) < N && k0 + lkc + 3 < Kp)
                vb = *reinterpret_cast<const float4*>(
                    Wp + (size_t)(n0 + lrow) * Kp + k0 + lkc);
            Bs[lkc + 0][lrow] = vb.x;
            Bs[lkc + 1][lrow] = vb.y;
            Bs[lkc + 2][lrow] = vb.z;
            Bs[lkc + 3][lrow] = vb.w;
            __syncthreads();
#pragma unroll
            for (int k = 0; k < 32; k++) {
                float2 a = *reinterpret_cast<const float2*>(&As[k][ty * 2]);
                float2 b = *reinterpret_cast<const float2*>(&Bs[k][tx * 2]);
                acc[0][0] = fmaf(a.x, b.x, acc[0][0]);
                acc[0][1] = fmaf(a.x, b.y, acc[0][1]);
                acc[1][0] = fmaf(a.y, b.x, acc[1][0]);
                acc[1][1] = fmaf(a.y, b.y, acc[1][1]);
            }
        }
    }

    float pb[2], pb2[2], prm[2], psc[2], pbe[2];
#pragma unroll
    for (int j = 0; j < 2; j++) {
        int col = n0 + tx * 2 + j;
        int cc  = (col < N) ? col : 0;
        pb[j]  = bias[cc];
        pb2[j] = (MODE == 1 && DUAL) ? bias2[cc] : 0.f;
        if (MODE == 2) {
            prm[j] = rm[cc];
            psc[j] = gam[cc] * rsqrtf(rv[cc] + EPSV);
            pbe[j] = bet[cc];
        }
    }
#pragma unroll
    for (int i = 0; i < 2; i++) {
        int row = m0 + ty * 2 + i;
        if (row >= M) continue;
#pragma unroll
        for (int j = 0; j < 2; j++) {
            int col = n0 + tx * 2 + j;
            if (col >= N) continue;
            float v = acc[i][j] + pb[j];
            if (MODE == 1) v = tanhf(v + pb2[j]);
            if (MODE == 2) v = (v - prm[j]) * psc[j] + pbe[j];
            C[(size_t)row * N + col] = v;
        }
    }
}

// ================= big GEMM (prex + autoenc), 128x64 tiles ==================
// MODE 0: C = acc + bias
// MODE 2: C = (acc + bias - rm)*(gam*rsqrt(rv+eps)) + beta
template<int MODE, int BM, int BN, int TM, int TN>
__global__ void __launch_bounds__(256) gemm_k(
    const float* __restrict__ A, const float* __restrict__ W,
    const float* __restrict__ bias,
    const float* __restrict__ gam, const float* __restrict__ rm,
    const float* __restrict__ rv,  const float* __restrict__ bet,
    float* __restrict__ C, int M, int N, int K,
    int rowDiv, int rowS1, int rowS2)
{
    constexpr int BK = 16;
    constexpr int TX = BN / TN;
    constexpr int TY = BM / TM;
    static_assert(TX * TY == 256, "thread count");

    __shared__ float As[BK][BM + 4];
    __shared__ float Bs[BK][BN + 4];

    const int tid = threadIdx.x;
    const int tx  = tid % TX;
    const int ty  = tid / TX;
    const int bm0 = blockIdx.y * BM;
    const int bn0 = blockIdx.x * BN;

    float acc[TM][TN];
#pragma unroll
    for (int i = 0; i < TM; i++)
#pragma unroll
        for (int j = 0; j < TN; j++) acc[i][j] = 0.f;

    constexpr int A4 = BM * BK / 4;
    constexpr int B4 = BN * BK / 4;

    for (int k0 = 0; k0 < K; k0 += BK) {
#pragma unroll
        for (int idx = tid; idx < A4; idx += 256) {
            int arow = idx >> 2;
            int ak4  = idx & 3;
            int m    = bm0 + arow;
            int kk   = k0 + ak4 * 4;
            float4 v = make_float4(0.f, 0.f, 0.f, 0.f);
            if (m < M && kk + 3 < K) {
                long off = (long)(m / rowDiv) * rowS1 + (long)(m % rowDiv) * rowS2;
                v = *reinterpret_cast<const float4*>(A + off + kk);
            }
            As[ak4 * 4 + 0][arow] = v.x;
            As[ak4 * 4 + 1][arow] = v.y;
            As[ak4 * 4 + 2][arow] = v.z;
            As[ak4 * 4 + 3][arow] = v.w;
        }
#pragma unroll
        for (int idx = tid; idx < B4; idx += 256) {
            int brow = idx >> 2;
            int bk4  = idx & 3;
            int n    = bn0 + brow;
            int kk   = k0 + bk4 * 4;
            float4 v = make_float4(0.f, 0.f, 0.f, 0.f);
            if (n < N && kk + 3 < K)
                v = *reinterpret_cast<const float4*>(W + (long)n * K + kk);
            Bs[bk4 * 4 + 0][brow] = v.x;
            Bs[bk4 * 4 + 1][brow] = v.y;
            Bs[bk4 * 4 + 2][brow] = v.z;
            Bs[bk4 * 4 + 3][brow] = v.w;
        }
        __syncthreads();
#pragma unroll
        for (int k = 0; k < BK; k++) {
            float a[TM], b[TN];
#pragma unroll
            for (int i = 0; i < TM; i++) a[i] = As[k][ty * TM + i];
#pragma unroll
            for (int j = 0; j < TN; j++) b[j] = Bs[k][tx * TN + j];
#pragma unroll
            for (int i = 0; i < TM; i++)
#pragma unroll
                for (int j = 0; j < TN; j++)
                    acc[i][j] = fmaf(a[i], b[j], acc[i][j]);
        }
        __syncthreads();
    }

    float pb[TN], prm[TN], psc[TN], pbe[TN];
#pragma unroll
    for (int j = 0; j < TN; j++) {
        int col = bn0 + tx * TN + j;
        int cc  = (col < N) ? col : 0;
        pb[j] = bias[cc];
        if (MODE == 2) {
            prm[j] = rm[cc];
            psc[j] = gam[cc] * rsqrtf(rv[cc] + EPSV);
            pbe[j] = bet[cc];
        }
    }
#pragma unroll
    for (int i = 0; i < TM; i++) {
        int row = bm0 + ty * TM + i;
        if (row >= M) continue;
#pragma unroll
        for (int j = 0; j < TN; j++) {
            int col = bn0 + tx * TN + j;
            if (col >= N) continue;
            float v = acc[i][j] + pb[j];
            if (MODE == 2) v = (v - prm[j]) * psc[j] + pbe[j];
            C[(long)row * N + col] = v;
        }
    }
}

// ----------------------------- misc kernels --------------------------------
__global__ void zero_k() { g_loss[0] = 0.0; g_loss[1] = 0.0; g_bar = 0; }

__global__ void loss1_k(const float* __restrict__ y, const float* __restrict__ x)
{
    __shared__ double sm[256];
    const int total = (TT - 1) * BSZ * FEAT;
    double s = 0.0;
    for (int idx = blockIdx.x * blockDim.x + threadIdx.x; idx < total;
         idx += gridDim.x * blockDim.x) {
        int f = idx & (FEAT - 1);
        int b = (idx >> 9) & (BSZ - 1);
        int t = idx >> 18;
        float d = y[idx] - x[(b * TTOT + t + 1) * FEAT + f];
        s += (double)d * (double)d;
    }
    sm[threadIdx.x] = s;
    __syncthreads();
    for (int o = 128; o > 0; o >>= 1) {
        if (threadIdx.x < o) sm[threadIdx.x] += sm[threadIdx.x + o];
        __syncthreads();
    }
    if (threadIdx.x == 0) atomicAdd(&g_loss[0], sm[0]);
}

__global__ void gather_k(const float* __restrict__ xall, const int* __restrict__ tt,
                         const float* __restrict__ x, float* __restrict__ out)
{
    __shared__ double sm[256];
    int idx = blockIdx.x * blockDim.x + threadIdx.x;
    int b = idx >> 9, f = idx & (FEAT - 1);
    int g = tt[b] - 1;
    float v = xall[(g * BSZ + b) * FEAT + f];
    out[idx] = v;
    float d = v - x[(b * TTOT + TTOT - 1) * FEAT + f];
    sm[threadIdx.x] = (double)d * (double)d;
    __syncthreads();
    for (int o = 128; o > 0; o >>= 1) {
        if (threadIdx.x < o) sm[threadIdx.x] += sm[threadIdx.x + o];
        __syncthreads();
    }
    if (threadIdx.x == 0) atomicAdd(&g_loss[1], sm[0]);
}

__global__ void fin_k(float* __restrict__ out)
{
    const double n1 = (double)(TT - 1) * BSZ * FEAT;
    const double n2 = (double)BSZ * FEAT;
    out[BSZ * FEAT] = (float)(g_loss[0] / (n1 * n1) + g_loss[1] / (n2 * n2));
}

// --------------------------- host orchestration ----------------------------
template<int MODE, int BM, int BN, int TM, int TN>
static void rungemm(const float* A, const float* W, const float* bias,
                    const float* gam, const float* rm,
                    const float* rv, const float* bet, float* C,
                    int M, int N, int K, int rowDiv, int rowS1, int rowS2)
{
    dim3 grid((N + BN - 1) / BN, (M + BM - 1) / BM);
    gemm_k<MODE, BM, BN, TM, TN><<<grid, 256>>>(A, W, bias, gam, rm, rv,
                                                bet, C, M, N, K,
                                                rowDiv, rowS1, rowS2);
}

extern "C" void kernel_launch(void* const* d_in, const int* in_sizes, int n_in,
                              void* d_out, int out_size)
{
    const float* x    = (const float*)d_in[0];
    const int*   tt   = (const int*)  d_in[1];
    const float* W_ih = (const float*)d_in[2];
    const float* W_hh = (const float*)d_in[3];
    const float* b_ih = (const float*)d_in[4];
    const float* b_hh = (const float*)d_in[5];
    const float* W1   = (const float*)d_in[6];
    const float* b1   = (const float*)d_in[7];
    const float* g1   = (const float*)d_in[8];
    const float* be1  = (const float*)d_in[9];
    const float* rm1  = (const float*)d_in[10];
    const float* rv1  = (const float*)d_in[11];
    const float* W2   = (const float*)d_in[12];
    const float* b2   = (const float*)d_in[13];
    const float* g2   = (const float*)d_in[14];
    const float* be2  = (const float*)d_in[15];
    const float* rm2  = (const float*)d_in[16];
    const float* rv2  = (const float*)d_in[17];
    const float* W3   = (const float*)d_in[18];
    const float* b3   = (const float*)d_in[19];
    const float* g3   = (const float*)d_in[20];
    const float* be3  = (const float*)d_in[21];
    const float* rm3  = (const float*)d_in[22];
    const float* rv3  = (const float*)d_in[23];
    float* out = (float*)d_out;

    float *prex, *hs, *z1, *z2, *y, *xall, *hA, *hB, *z1d, *z2d;
    cudaGetSymbolAddress((void**)&prex, g_prex);
    cudaGetSymbolAddress((void**)&hs,   g_hs);
    cudaGetSymbolAddress((void**)&z1,   g_z1);
    cudaGetSymbolAddress((void**)&z2,   g_z2);
    cudaGetSymbolAddress((void**)&y,    g_y);
    cudaGetSymbolAddress((void**)&xall, g_xall);
    cudaGetSymbolAddress((void**)&hA,   g_hA);
    cudaGetSymbolAddress((void**)&hB,   g_hB);
    cudaGetSymbolAddress((void**)&z1d,  g_z1d);
    cudaGetSymbolAddress((void**)&z2d,  g_z2d);

    const int BF   = BSZ * FEAT;
    const int BIGM = TT * BSZ;      // 32768
    const int NOROW = 1 << 30;      // identity row mapping

    static const int SCAN_SMEM = 512 * 68 * 4;   // 139264 B
    cudaFuncSetAttribute(scan_k, cudaFuncAttributeMaxDynamicSharedMemorySize,
                         SCAN_SMEM);

    zero_k<<<1, 1>>>();

    // 1. prex[t*B+b,:] = x[b,t,:] @ W_ih^T + b_ih   (one big GEMM)
    rungemm<0, 128, 64, 8, 4>(x, W_ih, b_ih, nullptr, nullptr, nullptr,
                              nullptr, prex, BIGM, FEAT, FEAT,
                              BSZ, FEAT, TTOT * FEAT);

    // 2. full RNN scan in ONE persistent kernel (W_hh resident in smem)
    scan_k<<<SCAN_GRID, 256, SCAN_SMEM>>>(prex, W_hh, b_hh, hs);

    // 3. autoencoder over all 32768 rows (dominant compute)
    rungemm<2, 128, 64, 8, 4>(hs, W1, b1, g1, rm1, rv1, be1,
                              z1, BIGM, HID, FEAT, NOROW, 0, FEAT);
    rungemm<2, 128, 64, 8, 4>(z1, W2, b2, g2, rm2, rv2, be2,
                              z2, BIGM, HID, HID, NOROW, 0, HID);
    rungemm<2, 128, 64, 8, 4>(z2, W3, b3, g3, rm3, rv3, be3,
                              y, BIGM, FEAT, HID, NOROW, 0, HID);

    // 4. loss1
    loss1_k<<<2048, 256>>>(y, x);

    // 5. decode: 16 serial iterations, 4 launches each (cell fused dual-A)
    const float* hprev = hs + (TT - 1) * BF;
    const float* xprev = y  + (TT - 1) * BF;
    for (int g = 0; g < GAPS; g++) {
        float* hcur = (g & 1) ? hB : hA;
        float* xcur = xall + g * BF;
        // h2 = tanh(x_hat@W_ih^T + h@W_hh^T + b_ih + b_hh)
        sgemm_k<1, 1><<<dim3(FEAT / 32, BSZ / 32), 256>>>(
            xprev, W_ih, FEAT, hprev, W_hh, FEAT,
            b_ih, b_hh, nullptr, nullptr, nullptr, nullptr,
            hcur, BSZ, FEAT);
        sgemm_k<2, 0><<<dim3((HID + 31) / 32, BSZ / 32), 256>>>(
            hcur, W1, FEAT, nullptr, nullptr, 0,
            b1, nullptr, g1, rm1, rv1, be1, z1d, BSZ, HID);
        sgemm_k<2, 0><<<dim3((HID + 31) / 32, BSZ / 32), 256>>>(
            z1d, W2, HID, nullptr, nullptr, 0,
            b2, nullptr, g2, rm2, rv2, be2, z2d, BSZ, HID);
        sgemm_k<2, 0><<<dim3(FEAT / 32, BSZ / 32), 256>>>(
            z2d, W3, HID, nullptr, nullptr, 0,
            b3, nullptr, g3, rm3, rv3, be3, xcur, BSZ, FEAT);
        hprev = hcur;
        xprev = xcur;
    }

    // 6. gather x_pred + loss2, finalize scalar loss
    gather_k<<<BF / 256, 256>>>(xall, tt, x, out);
    if (out_size > BSZ * FEAT) fin_k<<<1, 1>>>(out);
}

// round 6
// speedup vs baseline: 1.5513x; 1.2137x over previous
#include <cuda_runtime.h>
#include <cuda_bf16.h>
#include <math.h>
#include <stdint.h>

// Problem constants
#define BSZ   512
#define TT    64          // used timesteps (T_TOTAL-1)
#define TTOT  65
#define FEAT  512
#define HID   1000
#define GAPS  16
#define EPSV  1e-5f
#define SCAN_GRID 128     // persistent scan CTAs (<= 148 SMs, 1 CTA/SM)

// ---------------- scratch (device globals; allocation-free) ----------------
__device__ float g_prex[TT * BSZ * FEAT];     // x@W_ih^T + b_ih   (time-major)
__device__ float g_hs  [TT * BSZ * FEAT];     // hidden states     (time-major)
__device__ float g_z1  [TT * BSZ * HID];
__device__ float g_z2  [TT * BSZ * HID];
__device__ float g_y   [TT * BSZ * FEAT];
__device__ float g_xall[GAPS * BSZ * FEAT];
__device__ float g_hA  [BSZ * FEAT];
__device__ float g_hB  [BSZ * FEAT];
__device__ float g_z1d [BSZ * HID];
__device__ float g_z2d [BSZ * HID];
__device__ double g_loss[2];
__device__ int    g_bar;                      // software grid barrier counter

// ---------------- tf32 helpers ----------------
__device__ __forceinline__ uint32_t f2tf(float f) {
    uint32_t u;
    asm("cvt.rna.tf32.f32 %0, %1;" : "=r"(u) : "f"(f));
    return u;
}
__device__ __forceinline__ void mma_tf32(float* c, const uint32_t* a,
                                         const uint32_t* b) {
    asm volatile(
        "mma.sync.aligned.m16n8k8.row.col.f32.tf32.tf32.f32 "
        "{%0,%1,%2,%3}, {%4,%5,%6,%7}, {%8,%9}, {%0,%1,%2,%3};"
        : "+f"(c[0]), "+f"(c[1]), "+f"(c[2]), "+f"(c[3])
        : "r"(a[0]), "r"(a[1]), "r"(a[2]), "r"(a[3]), "r"(b[0]), "r"(b[1]));
}

// ============== tf32 tensor-core GEMM: C = ep(A @ W^T + bias) ===============
// Tile: 128(M) x 64(N) x 32(K). 8 warps = 4(m) x 2(n); warp tile 32x32.
// Smem XOR-swizzled so all fragment LDS are bank-conflict-free.
// MODE 0: C = acc + bias
// MODE 2: C = (acc + bias - rm)*(gam*rsqrt(rv+eps)) + beta
template<int MODE>
__global__ void __launch_bounds__(256) tgemm_k(
    const float* __restrict__ A, const float* __restrict__ W,
    const float* __restrict__ bias,
    const float* __restrict__ gam, const float* __restrict__ rm,
    const float* __restrict__ rv,  const float* __restrict__ bet,
    float* __restrict__ C, int M, int N, int K,
    int rowDiv, int rowS1, int rowS2)
{
    __shared__ uint32_t As[128 * 32];   // [m][k^((m&7)<<2)]
    __shared__ uint32_t Bs[64 * 32];    // [n][k^((n&7)<<2)]

    const int tid  = threadIdx.x;
    const int lane = tid & 31;
    const int warp = tid >> 5;
    const int gid  = lane >> 2;     // 0..7
    const int tg   = lane & 3;      // 0..3
    const int wm   = warp & 3;      // 4 m-warps
    const int wn   = warp >> 2;     // 2 n-warps
    const int bm0  = blockIdx.y * 128;
    const int bn0  = blockIdx.x * 64;
    const int swz  = gid << 2;      // per-thread swizzle constant

    float c[2][4][4];
#pragma unroll
    for (int i = 0; i < 2; i++)
#pragma unroll
        for (int j = 0; j < 4; j++)
#pragma unroll
            for (int r = 0; r < 4; r++) c[i][j][r] = 0.f;

    const int KC = (K + 31) / 32;
    for (int kc = 0; kc < KC; kc++) {
        const int k0 = kc * 32;
        __syncthreads();
        // ---- stage A tile: 128x32, 4 float4 per thread ----
#pragma unroll
        for (int i = 0; i < 4; i++) {
            int idx = tid + i * 256;            // 0..1023
            int m   = idx >> 3;
            int kq  = (idx & 7) * 4;
            int gm  = bm0 + m;
            float4 v = make_float4(0.f, 0.f, 0.f, 0.f);
            if (k0 + kq + 3 < K) {
                long off = (long)(gm / rowDiv) * rowS1 +
                           (long)(gm % rowDiv) * rowS2;
                v = *reinterpret_cast<const float4*>(A + off + k0 + kq);
            }
            uint32_t* d = &As[m * 32 + (kq ^ ((m & 7) << 2))];
            d[0] = f2tf(v.x); d[1] = f2tf(v.y);
            d[2] = f2tf(v.z); d[3] = f2tf(v.w);
        }
        // ---- stage B tile: 64x32, 2 float4 per thread ----
#pragma unroll
        for (int i = 0; i < 2; i++) {
            int idx = tid + i * 256;            // 0..511
            int n   = idx >> 3;
            int kq  = (idx & 7) * 4;
            int gn  = bn0 + n;
            float4 v = make_float4(0.f, 0.f, 0.f, 0.f);
            if (gn < N && k0 + kq + 3 < K)
                v = *reinterpret_cast<const float4*>(W + (long)gn * K + k0 + kq);
            uint32_t* d = &Bs[n * 32 + (kq ^ ((n & 7) << 2))];
            d[0] = f2tf(v.x); d[1] = f2tf(v.y);
            d[2] = f2tf(v.z); d[3] = f2tf(v.w);
        }
        __syncthreads();
        // ---- compute: 4 k-steps of 8 ----
#pragma unroll
        for (int kt = 0; kt < 4; kt++) {
            const int klo = (kt * 8 + tg) ^ swz;
            const int khi = (kt * 8 + tg + 4) ^ swz;
            uint32_t bfr[4][2];
#pragma unroll
            for (int nt = 0; nt < 4; nt++) {
                int nrow = (wn * 32 + nt * 8 + gid) * 32;
                bfr[nt][0] = Bs[nrow + klo];
                bfr[nt][1] = Bs[nrow + khi];
            }
            uint32_t afr[2][4];
#pragma unroll
            for (int mt = 0; mt < 2; mt++) {
                int mrow = (wm * 32 + mt * 16 + gid) * 32;
                afr[mt][0] = As[mrow + klo];
                afr[mt][1] = As[mrow + 8 * 32 + klo];
                afr[mt][2] = As[mrow + khi];
                afr[mt][3] = As[mrow + 8 * 32 + khi];
            }
#pragma unroll
            for (int mt = 0; mt < 2; mt++)
#pragma unroll
                for (int nt = 0; nt < 4; nt++)
                    mma_tf32(c[mt][nt], afr[mt], bfr[nt]);
        }
    }

    // ---- epilogue ----
#pragma unroll
    for (int nt = 0; nt < 4; nt++) {
#pragma unroll
        for (int e = 0; e < 2; e++) {
            int col = bn0 + wn * 32 + nt * 8 + tg * 2 + e;
            if (col >= N) continue;
            float pb = bias[col];
            float prm = 0.f, psc = 0.f, pbe = 0.f;
            if (MODE == 2) {
                prm = rm[col];
                psc = gam[col] * rsqrtf(rv[col] + EPSV);
                pbe = bet[col];
            }
#pragma unroll
            for (int mt = 0; mt < 2; mt++)
#pragma unroll
                for (int h = 0; h < 2; h++) {
                    int row = bm0 + wm * 32 + mt * 16 + gid + h * 8;
                    float v = c[mt][nt][h * 2 + e] + pb;
                    if (MODE == 2) v = (v - prm) * psc + pbe;
                    C[(long)row * N + col] = v;
                }
        }
    }
}

// ======================= persistent RNN scan kernel =========================
__global__ void __launch_bounds__(256) scan_k(const float* __restrict__ prex,
                                              const float* __restrict__ W_hh,
                                              const float* __restrict__ b_hh,
                                              float* __restrict__ hs)
{
    extern __shared__ float Wt[];             // [512][68]
    __shared__ float As[32][34];              // A chunk, As[k][m]

    const int tid = threadIdx.x;
    const int nb  = blockIdx.x & 7;
    const int mb  = blockIdx.x >> 3;
    const int n0  = nb * 64;
    const int m0  = mb * 32;
    const int tx  = tid & 15;
    const int ty  = tid >> 4;

    for (int idx = tid; idx < 64 * 512; idx += 256) {
        int n = idx >> 9, k = idx & 511;
        Wt[k * 68 + n] = W_hh[(n0 + n) * FEAT + k];
    }
    float bh[4];
#pragma unroll
    for (int j = 0; j < 4; j++) bh[j] = b_hh[n0 + tx * 4 + j];
    __syncthreads();

    const int lrow = tid >> 3;
    const int lkc  = (tid & 7) * 4;

    int tgt = 0;
    for (int s = 0; s < TT; s++) {
        float acc[2][4];
#pragma unroll
        for (int i = 0; i < 2; i++)
#pragma unroll
            for (int j = 0; j < 4; j++) acc[i][j] = 0.f;

        if (s > 0) {
            const float* hp = hs + (size_t)(s - 1) * BSZ * FEAT;
            float4 v = *reinterpret_cast<const float4*>(
                hp + (m0 + lrow) * FEAT + lkc);
            for (int k0 = 0; k0 < FEAT; k0 += 32) {
                __syncthreads();
                As[lkc + 0][lrow] = v.x;
                As[lkc + 1][lrow] = v.y;
                As[lkc + 2][lrow] = v.z;
                As[lkc + 3][lrow] = v.w;
                __syncthreads();
                if (k0 + 32 < FEAT)
                    v = *reinterpret_cast<const float4*>(
                        hp + (m0 + lrow) * FEAT + k0 + 32 + lkc);
#pragma unroll
                for (int k = 0; k < 32; k++) {
                    float2 a = *reinterpret_cast<const float2*>(&As[k][ty * 2]);
                    float4 b = *reinterpret_cast<const float4*>(
                        &Wt[(k0 + k) * 68 + tx * 4]);
                    acc[0][0] = fmaf(a.x, b.x, acc[0][0]);
                    acc[0][1] = fmaf(a.x, b.y, acc[0][1]);
                    acc[0][2] = fmaf(a.x, b.z, acc[0][2]);
                    acc[0][3] = fmaf(a.x, b.w, acc[0][3]);
                    acc[1][0] = fmaf(a.y, b.x, acc[1][0]);
                    acc[1][1] = fmaf(a.y, b.y, acc[1][1]);
                    acc[1][2] = fmaf(a.y, b.z, acc[1][2]);
                    acc[1][3] = fmaf(a.y, b.w, acc[1][3]);
                }
            }
        }
        const float* px = prex + (size_t)s * BSZ * FEAT;
        float*       ho = hs   + (size_t)s * BSZ * FEAT;
#pragma unroll
        for (int i = 0; i < 2; i++) {
            int m = m0 + ty * 2 + i;
#pragma unroll
            for (int j = 0; j < 4; j++) {
                int n = n0 + tx * 4 + j;
                ho[m * FEAT + n] = tanhf(acc[i][j] + px[m * FEAT + n] + bh[j]);
            }
        }
        tgt += SCAN_GRID;
        __syncthreads();
        if (tid == 0) {
            __threadfence();
            atomicAdd(&g_bar, 1);
            while (*(volatile int*)&g_bar < tgt) __nanosleep(64);
            __threadfence();
        }
        __syncthreads();
    }
}

// ================== small GEMM (decode): 32x32 tile, BK=32 ==================
template<int MODE, int DUAL>
__global__ void __launch_bounds__(256) sgemm_k(
    const float* __restrict__ A,  const float* __restrict__ W,  int K,
    const float* __restrict__ A2, const float* __restrict__ W2, int K2,
    const float* __restrict__ bias, const float* __restrict__ bias2,
    const float* __restrict__ gam, const float* __restrict__ rm,
    const float* __restrict__ rv,  const float* __restrict__ bet,
    float* __restrict__ C, int M, int N)
{
    __shared__ float As[32][34];
    __shared__ float Bs[32][34];
    const int tid = threadIdx.x;
    const int tx  = tid & 15;
    const int ty  = tid >> 4;
    const int m0  = blockIdx.y * 32;
    const int n0  = blockIdx.x * 32;
    const int lrow = tid >> 3;
    const int lkc  = (tid & 7) * 4;

    float acc[2][2] = {{0.f, 0.f}, {0.f, 0.f}};

#pragma unroll
    for (int pass = 0; pass < 1 + DUAL; pass++) {
        const float* Ap = pass ? A2 : A;
        const float* Wp = pass ? W2 : W;
        const int    Kp = pass ? K2 : K;
        for (int k0 = 0; k0 < Kp; k0 += 32) {
            __syncthreads();
            float4 va = make_float4(0.f, 0.f, 0.f, 0.f);
            if (k0 + lkc + 3 < Kp)
                va = *reinterpret_cast<const float4*>(
                    Ap + (size_t)(m0 + lrow) * Kp + k0 + lkc);
            As[lkc + 0][lrow] = va.x;
            As[lkc + 1][lrow] = va.y;
            As[lkc + 2][lrow] = va.z;
            As[lkc + 3][lrow] = va.w;
            float4 vb = make_float4(0.f, 0.f, 0.f, 0.f);
            if ((n0 + lrow) < N && k0 + lkc + 3 < Kp)
                vb = *reinterpret_cast<const float4*>(
                    Wp + (size_t)(n0 + lrow) * Kp + k0 + lkc);
            Bs[lkc + 0][lrow] = vb.x;
            Bs[lkc + 1][lrow] = vb.y;
            Bs[lkc + 2][lrow] = vb.z;
            Bs[lkc + 3][lrow] = vb.w;
            __syncthreads();
#pragma unroll
            for (int k = 0; k < 32; k++) {
                float2 a = *reinterpret_cast<const float2*>(&As[k][ty * 2]);
                float2 b = *reinterpret_cast<const float2*>(&Bs[k][tx * 2]);
                acc[0][0] = fmaf(a.x, b.x, acc[0][0]);
                acc[0][1] = fmaf(a.x, b.y, acc[0][1]);
                acc[1][0] = fmaf(a.y, b.x, acc[1][0]);
                acc[1][1] = fmaf(a.y, b.y, acc[1][1]);
            }
        }
    }

    float pb[2], pb2[2], prm[2], psc[2], pbe[2];
#pragma unroll
    for (int j = 0; j < 2; j++) {
        int col = n0 + tx * 2 + j;
        int cc  = (col < N) ? col : 0;
        pb[j]  = bias[cc];
        pb2[j] = (MODE == 1 && DUAL) ? bias2[cc] : 0.f;
        if (MODE == 2) {
            prm[j] = rm[cc];
            psc[j] = gam[cc] * rsqrtf(rv[cc] + EPSV);
            pbe[j] = bet[cc];
        }
    }
#pragma unroll
    for (int i = 0; i < 2; i++) {
        int row = m0 + ty * 2 + i;
        if (row >= M) continue;
#pragma unroll
        for (int j = 0; j < 2; j++) {
            int col = n0 + tx * 2 + j;
            if (col >= N) continue;
            float v = acc[i][j] + pb[j];
            if (MODE == 1) v = tanhf(v + pb2[j]);
            if (MODE == 2) v = (v - prm[j]) * psc[j] + pbe[j];
            C[(size_t)row * N + col] = v;
        }
    }
}

// ----------------------------- misc kernels --------------------------------
__global__ void zero_k() { g_loss[0] = 0.0; g_loss[1] = 0.0; g_bar = 0; }

__global__ void loss1_k(const float* __restrict__ y, const float* __restrict__ x)
{
    __shared__ double sm[256];
    const int total = (TT - 1) * BSZ * FEAT;
    double s = 0.0;
    for (int idx = blockIdx.x * blockDim.x + threadIdx.x; idx < total;
         idx += gridDim.x * blockDim.x) {
        int f = idx & (FEAT - 1);
        int b = (idx >> 9) & (BSZ - 1);
        int t = idx >> 18;
        float d = y[idx] - x[(b * TTOT + t + 1) * FEAT + f];
        s += (double)d * (double)d;
    }
    sm[threadIdx.x] = s;
    __syncthreads();
    for (int o = 128; o > 0; o >>= 1) {
        if (threadIdx.x < o) sm[threadIdx.x] += sm[threadIdx.x + o];
        __syncthreads();
    }
    if (threadIdx.x == 0) atomicAdd(&g_loss[0], sm[0]);
}

__global__ void gather_k(const float* __restrict__ xall, const int* __restrict__ tt,
                         const float* __restrict__ x, float* __restrict__ out)
{
    __shared__ double sm[256];
    int idx = blockIdx.x * blockDim.x + threadIdx.x;
    int b = idx >> 9, f = idx & (FEAT - 1);
    int g = tt[b] - 1;
    float v = xall[(g * BSZ + b) * FEAT + f];
    out[idx] = v;
    float d = v - x[(b * TTOT + TTOT - 1) * FEAT + f];
    sm[threadIdx.x] = (double)d * (double)d;
    __syncthreads();
    for (int o = 128; o > 0; o >>= 1) {
        if (threadIdx.x < o) sm[threadIdx.x] += sm[threadIdx.x + o];
        __syncthreads();
    }
    if (threadIdx.x == 0) atomicAdd(&g_loss[1], sm[0]);
}

__global__ void fin_k(float* __restrict__ out)
{
    const double n1 = (double)(TT - 1) * BSZ * FEAT;
    const double n2 = (double)BSZ * FEAT;
    out[BSZ * FEAT] = (float)(g_loss[0] / (n1 * n1) + g_loss[1] / (n2 * n2));
}

// --------------------------- host orchestration ----------------------------
template<int MODE>
static void runtg(const float* A, const float* W, const float* bias,
                  const float* gam, const float* rm,
                  const float* rv, const float* bet, float* C,
                  int M, int N, int K, int rowDiv, int rowS1, int rowS2)
{
    dim3 grid((N + 63) / 64, (M + 127) / 128);
    tgemm_k<MODE><<<grid, 256>>>(A, W, bias, gam, rm, rv, bet, C,
                                 M, N, K, rowDiv, rowS1, rowS2);
}

extern "C" void kernel_launch(void* const* d_in, const int* in_sizes, int n_in,
                              void* d_out, int out_size)
{
    const float* x    = (const float*)d_in[0];
    const int*   tt   = (const int*)  d_in[1];
    const float* W_ih = (const float*)d_in[2];
    const float* W_hh = (const float*)d_in[3];
    const float* b_ih = (const float*)d_in[4];
    const float* b_hh = (const float*)d_in[5];
    const float* W1   = (const float*)d_in[6];
    const float* b1   = (const float*)d_in[7];
    const float* g1   = (const float*)d_in[8];
    const float* be1  = (const float*)d_in[9];
    const float* rm1  = (const float*)d_in[10];
    const float* rv1  = (const float*)d_in[11];
    const float* W2   = (const float*)d_in[12];
    const float* b2   = (const float*)d_in[13];
    const float* g2   = (const float*)d_in[14];
    const float* be2  = (const float*)d_in[15];
    const float* rm2  = (const float*)d_in[16];
    const float* rv2  = (const float*)d_in[17];
    const float* W3   = (const float*)d_in[18];
    const float* b3   = (const float*)d_in[19];
    const float* g3   = (const float*)d_in[20];
    const float* be3  = (const float*)d_in[21];
    const float* rm3  = (const float*)d_in[22];
    const float* rv3  = (const float*)d_in[23];
    float* out = (float*)d_out;

    float *prex, *hs, *z1, *z2, *y, *xall, *hA, *hB, *z1d, *z2d;
    cudaGetSymbolAddress((void**)&prex, g_prex);
    cudaGetSymbolAddress((void**)&hs,   g_hs);
    cudaGetSymbolAddress((void**)&z1,   g_z1);
    cudaGetSymbolAddress((void**)&z2,   g_z2);
    cudaGetSymbolAddress((void**)&y,    g_y);
    cudaGetSymbolAddress((void**)&xall, g_xall);
    cudaGetSymbolAddress((void**)&hA,   g_hA);
    cudaGetSymbolAddress((void**)&hB,   g_hB);
    cudaGetSymbolAddress((void**)&z1d,  g_z1d);
    cudaGetSymbolAddress((void**)&z2d,  g_z2d);

    const int BF   = BSZ * FEAT;
    const int BIGM = TT * BSZ;      // 32768
    const int NOROW = 1 << 30;      // identity row mapping

    static const int SCAN_SMEM = 512 * 68 * 4;   // 139264 B
    cudaFuncSetAttribute(scan_k, cudaFuncAttributeMaxDynamicSharedMemorySize,
                         SCAN_SMEM);

    zero_k<<<1, 1>>>();

    // 1. prex[t*B+b,:] = x[b,t,:] @ W_ih^T + b_ih   (tf32 tensor GEMM)
    runtg<0>(x, W_ih, b_ih, nullptr, nullptr, nullptr, nullptr,
             prex, BIGM, FEAT, FEAT, BSZ, FEAT, TTOT * FEAT);

    // 2. full RNN scan in ONE persistent kernel (fp32, W_hh in smem)
    scan_k<<<SCAN_GRID, 256, SCAN_SMEM>>>(prex, W_hh, b_hh, hs);

    // 3. autoencoder over all 32768 rows (tf32 tensor GEMMs)
    runtg<2>(hs, W1, b1, g1, rm1, rv1, be1, z1, BIGM, HID, FEAT,
             NOROW, 0, FEAT);
    runtg<2>(z1, W2, b2, g2, rm2, rv2, be2, z2, BIGM, HID, HID,
             NOROW, 0, HID);
    runtg<2>(z2, W3, b3, g3, rm3, rv3, be3, y, BIGM, FEAT, HID,
             NOROW, 0, HID);

    // 4. loss1
    loss1_k<<<2048, 256>>>(y, x);

    // 5. decode: 16 serial iterations, 4 launches each (fp32 SIMT)
    const float* hprev = hs + (TT - 1) * BF;
    const float* xprev = y  + (TT - 1) * BF;
    for (int g = 0; g < GAPS; g++) {
        float* hcur = (g & 1) ? hB : hA;
        float* xcur = xall + g * BF;
        sgemm_k<1, 1><<<dim3(FEAT / 32, BSZ / 32), 256>>>(
            xprev, W_ih, FEAT, hprev, W_hh, FEAT,
            b_ih, b_hh, nullptr, nullptr, nullptr, nullptr,
            hcur, BSZ, FEAT);
        sgemm_k<2, 0><<<dim3((HID + 31) / 32, BSZ / 32), 256>>>(
            hcur, W1, FEAT, nullptr, nullptr, 0,
            b1, nullptr, g1, rm1, rv1, be1, z1d, BSZ, HID);
        sgemm_k<2, 0><<<dim3((HID + 31) / 32, BSZ / 32), 256>>>(
            z1d, W2, HID, nullptr, nullptr, 0,
            b2, nullptr, g2, rm2, rv2, be2, z2d, BSZ, HID);
        sgemm_k<2, 0><<<dim3(FEAT / 32, BSZ / 32), 256>>>(
            z2d, W3, HID, nullptr, nullptr, 0,
            b3, nullptr, g3, rm3, rv3, be3, xcur, BSZ, FEAT);
        hprev = hcur;
        xprev = xcur;
    }

    // 6. gather x_pred + loss2, finalize scalar loss
    gather_k<<<BF / 256, 256>>>(xall, tt, x, out);
    if (out_size > BSZ * FEAT) fin_k<<<1, 1>>>(out);
}

// round 7
// speedup vs baseline: 1.9500x; 1.2570x over previous
#include <cuda_runtime.h>
#include <cuda_bf16.h>
#include <math.h>
#include <stdint.h>

// Problem constants
#define BSZ   512
#define TT    64          // used timesteps (T_TOTAL-1)
#define TTOT  65
#define FEAT  512
#define HID   1000
#define GAPS  16
#define EPSV  1e-5f
#define SCAN_GRID 128     // persistent scan CTAs (<= 148 SMs, 1 CTA/SM)

// ---------------- scratch (device globals; allocation-free) ----------------
__device__ float g_prex[TT * BSZ * FEAT];     // x@W_ih^T + b_ih   (time-major)
__device__ float g_hs  [TT * BSZ * FEAT];     // hidden states     (time-major)
__device__ float g_z1  [TT * BSZ * HID];
__device__ float g_z2  [TT * BSZ * HID];
__device__ float g_y   [TT * BSZ * FEAT];
__device__ float g_xall[GAPS * BSZ * FEAT];
__device__ float g_hA  [BSZ * FEAT];
__device__ float g_hB  [BSZ * FEAT];
__device__ float g_z1d [BSZ * HID];
__device__ float g_z2d [BSZ * HID];
__device__ double g_loss[2];
__device__ int    g_bar;                      // software grid barrier counter

// ---------------- tf32 helpers ----------------
__device__ __forceinline__ uint32_t f2tf(float f) {
    uint32_t u;
    asm("cvt.rna.tf32.f32 %0, %1;" : "=r"(u) : "f"(f));
    return u;
}
__device__ __forceinline__ void mma_tf32(float* c, const uint32_t* a,
                                         const uint32_t* b) {
    asm volatile(
        "mma.sync.aligned.m16n8k8.row.col.f32.tf32.tf32.f32 "
        "{%0,%1,%2,%3}, {%4,%5,%6,%7}, {%8,%9}, {%0,%1,%2,%3};"
        : "+f"(c[0]), "+f"(c[1]), "+f"(c[2]), "+f"(c[3])
        : "r"(a[0]), "r"(a[1]), "r"(a[2]), "r"(a[3]), "r"(b[0]), "r"(b[1]));
}

// ============== tf32 tensor-core GEMM (double-buffered) =====================
// C = ep( A@W^T [+ A2@W2^T] + bias )
// Tile: 128(M) x 64(N) x 32(K). 8 warps = 4(m) x 2(n); warp tile 32x32.
// Smem XOR-swizzled (k ^ ((m&7)<<2)) -> conflict-free fragment LDS.
// MODE 0: C = acc + bias
// MODE 1: C = tanh(acc + bias + bias2)      (RNN cell; DUAL=1)
// MODE 2: C = (acc + bias - rm)*(gam*rsqrt(rv+eps)) + beta
// M must be a multiple of 128.
template<int MODE, int DUAL>
__global__ void __launch_bounds__(256) tgemm_k(
    const float* __restrict__ A,  const float* __restrict__ W,  int K,
    const float* __restrict__ A2, const float* __restrict__ W2, int K2,
    const float* __restrict__ bias, const float* __restrict__ bias2,
    const float* __restrict__ gam, const float* __restrict__ rm,
    const float* __restrict__ rv,  const float* __restrict__ bet,
    float* __restrict__ C, int M, int N,
    int rowDiv, int rowS1, int rowS2)
{
    __shared__ uint32_t As[2][128 * 32];   // 32 KB
    __shared__ uint32_t Bs[2][64 * 32];    // 16 KB

    const int tid  = threadIdx.x;
    const int lane = tid & 31;
    const int warp = tid >> 5;
    const int gid  = lane >> 2;     // 0..7
    const int tg   = lane & 3;      // 0..3
    const int wm   = warp & 3;      // 4 m-warps
    const int wn   = warp >> 2;     // 2 n-warps
    const int bm0  = blockIdx.y * 128;
    const int bn0  = blockIdx.x * 64;
    const int swz  = gid << 2;      // per-thread swizzle constant

    float c[2][4][4];
#pragma unroll
    for (int i = 0; i < 2; i++)
#pragma unroll
        for (int j = 0; j < 4; j++)
#pragma unroll
            for (int r = 0; r < 4; r++) c[i][j][r] = 0.f;

    const int KC1 = (K + 31) >> 5;
    const int KC2 = DUAL ? ((K2 + 31) >> 5) : 0;
    const int KCT = KC1 + KC2;

    float4 va[4], vb[2];

    // ---- load chunk t from global into staging regs ----
    auto loadg = [&](int t) {
        const float* Ap; const float* Wp; int Kp, k0; bool p0;
        if (t < KC1) { Ap = A;  Wp = W;  Kp = K;  k0 = t << 5;          p0 = true; }
        else         { Ap = A2; Wp = W2; Kp = K2; k0 = (t - KC1) << 5;  p0 = false; }
#pragma unroll
        for (int i = 0; i < 4; i++) {
            int idx = tid + i * 256;
            int m   = idx >> 3;
            int kq  = (idx & 7) * 4;
            int gm  = bm0 + m;
            float4 v = make_float4(0.f, 0.f, 0.f, 0.f);
            if (k0 + kq + 3 < Kp) {
                long off = p0 ? ((long)(gm / rowDiv) * rowS1 +
                                 (long)(gm % rowDiv) * rowS2)
                              : (long)gm * K2;
                v = *reinterpret_cast<const float4*>(Ap + off + k0 + kq);
            }
            va[i] = v;
        }
#pragma unroll
        for (int i = 0; i < 2; i++) {
            int idx = tid + i * 256;
            int n   = idx >> 3;
            int kq  = (idx & 7) * 4;
            int gn  = bn0 + n;
            float4 v = make_float4(0.f, 0.f, 0.f, 0.f);
            if (gn < N && k0 + kq + 3 < Kp)
                v = *reinterpret_cast<const float4*>(Wp + (long)gn * Kp + k0 + kq);
            vb[i] = v;
        }
    };
    // ---- store staging regs (tf32-converted) into smem buffer ----
    auto stores = [&](int buf) {
#pragma unroll
        for (int i = 0; i < 4; i++) {
            int idx = tid + i * 256;
            int m   = idx >> 3;
            int kq  = (idx & 7) * 4;
            uint32_t* d = &As[buf][m * 32 + (kq ^ ((m & 7) << 2))];
            d[0] = f2tf(va[i].x); d[1] = f2tf(va[i].y);
            d[2] = f2tf(va[i].z); d[3] = f2tf(va[i].w);
        }
#pragma unroll
        for (int i = 0; i < 2; i++) {
            int idx = tid + i * 256;
            int n   = idx >> 3;
            int kq  = (idx & 7) * 4;
            uint32_t* d = &Bs[buf][n * 32 + (kq ^ ((n & 7) << 2))];
            d[0] = f2tf(vb[i].x); d[1] = f2tf(vb[i].y);
            d[2] = f2tf(vb[i].z); d[3] = f2tf(vb[i].w);
        }
    };

    loadg(0);
    stores(0);
    __syncthreads();

    for (int t = 0; t < KCT; t++) {
        const int cur = t & 1;
        const bool more = (t + 1 < KCT);
        if (more) loadg(t + 1);              // LDGs overlap with MMA below
        // ---- compute from buffer cur: 4 k-steps of 8 ----
#pragma unroll
        for (int kt = 0; kt < 4; kt++) {
            const int klo = (kt * 8 + tg) ^ swz;
            const int khi = (kt * 8 + tg + 4) ^ swz;
            uint32_t bfr[4][2];
#pragma unroll
            for (int nt = 0; nt < 4; nt++) {
                int nrow = (wn * 32 + nt * 8 + gid) * 32;
                bfr[nt][0] = Bs[cur][nrow + klo];
                bfr[nt][1] = Bs[cur][nrow + khi];
            }
            uint32_t afr[2][4];
#pragma unroll
            for (int mt = 0; mt < 2; mt++) {
                int mrow = (wm * 32 + mt * 16 + gid) * 32;
                afr[mt][0] = As[cur][mrow + klo];
                afr[mt][1] = As[cur][mrow + 8 * 32 + klo];
                afr[mt][2] = As[cur][mrow + khi];
                afr[mt][3] = As[cur][mrow + 8 * 32 + khi];
            }
#pragma unroll
            for (int mt = 0; mt < 2; mt++)
#pragma unroll
                for (int nt = 0; nt < 4; nt++)
                    mma_tf32(c[mt][nt], afr[mt], bfr[nt]);
        }
        if (more) stores(cur ^ 1);
        __syncthreads();
    }

    // ---- epilogue ----
#pragma unroll
    for (int nt = 0; nt < 4; nt++) {
#pragma unroll
        for (int e = 0; e < 2; e++) {
            int col = bn0 + wn * 32 + nt * 8 + tg * 2 + e;
            if (col >= N) continue;
            float pb  = bias[col];
            float pb2 = (MODE == 1) ? bias2[col] : 0.f;
            float prm = 0.f, psc = 0.f, pbe = 0.f;
            if (MODE == 2) {
                prm = rm[col];
                psc = gam[col] * rsqrtf(rv[col] + EPSV);
                pbe = bet[col];
            }
#pragma unroll
            for (int mt = 0; mt < 2; mt++)
#pragma unroll
                for (int h = 0; h < 2; h++) {
                    int row = bm0 + wm * 32 + mt * 16 + gid + h * 8;
                    float v = c[mt][nt][h * 2 + e] + pb;
                    if (MODE == 1) v = tanhf(v + pb2);
                    if (MODE == 2) v = (v - prm) * psc + pbe;
                    C[(long)row * N + col] = v;
                }
        }
    }
}

// ======================= persistent RNN scan kernel =========================
__global__ void __launch_bounds__(256) scan_k(const float* __restrict__ prex,
                                              const float* __restrict__ W_hh,
                                              const float* __restrict__ b_hh,
                                              float* __restrict__ hs)
{
    extern __shared__ float Wt[];             // [512][68]
    __shared__ float As[32][34];              // A chunk, As[k][m]

    const int tid = threadIdx.x;
    const int nb  = blockIdx.x & 7;
    const int mb  = blockIdx.x >> 3;
    const int n0  = nb * 64;
    const int m0  = mb * 32;
    const int tx  = tid & 15;
    const int ty  = tid >> 4;

    for (int idx = tid; idx < 64 * 512; idx += 256) {
        int n = idx >> 9, k = idx & 511;
        Wt[k * 68 + n] = W_hh[(n0 + n) * FEAT + k];
    }
    float bh[4];
#pragma unroll
    for (int j = 0; j < 4; j++) bh[j] = b_hh[n0 + tx * 4 + j];
    __syncthreads();

    const int lrow = tid >> 3;
    const int lkc  = (tid & 7) * 4;

    int tgt = 0;
    for (int s = 0; s < TT; s++) {
        float acc[2][4];
#pragma unroll
        for (int i = 0; i < 2; i++)
#pragma unroll
            for (int j = 0; j < 4; j++) acc[i][j] = 0.f;

        if (s > 0) {
            const float* hp = hs + (size_t)(s - 1) * BSZ * FEAT;
            float4 v = *reinterpret_cast<const float4*>(
                hp + (m0 + lrow) * FEAT + lkc);
            for (int k0 = 0; k0 < FEAT; k0 += 32) {
                __syncthreads();
                As[lkc + 0][lrow] = v.x;
                As[lkc + 1][lrow] = v.y;
                As[lkc + 2][lrow] = v.z;
                As[lkc + 3][lrow] = v.w;
                __syncthreads();
                if (k0 + 32 < FEAT)
                    v = *reinterpret_cast<const float4*>(
                        hp + (m0 + lrow) * FEAT + k0 + 32 + lkc);
#pragma unroll
                for (int k = 0; k < 32; k++) {
                    float2 a = *reinterpret_cast<const float2*>(&As[k][ty * 2]);
                    float4 b = *reinterpret_cast<const float4*>(
                        &Wt[(k0 + k) * 68 + tx * 4]);
                    acc[0][0] = fmaf(a.x, b.x, acc[0][0]);
                    acc[0][1] = fmaf(a.x, b.y, acc[0][1]);
                    acc[0][2] = fmaf(a.x, b.z, acc[0][2]);
                    acc[0][3] = fmaf(a.x, b.w, acc[0][3]);
                    acc[1][0] = fmaf(a.y, b.x, acc[1][0]);
                    acc[1][1] = fmaf(a.y, b.y, acc[1][1]);
                    acc[1][2] = fmaf(a.y, b.z, acc[1][2]);
                    acc[1][3] = fmaf(a.y, b.w, acc[1][3]);
                }
            }
        }
        const float* px = prex + (size_t)s * BSZ * FEAT;
        float*       ho = hs   + (size_t)s * BSZ * FEAT;
#pragma unroll
        for (int i = 0; i < 2; i++) {
            int m = m0 + ty * 2 + i;
#pragma unroll
            for (int j = 0; j < 4; j++) {
                int n = n0 + tx * 4 + j;
                ho[m * FEAT + n] = tanhf(acc[i][j] + px[m * FEAT + n] + bh[j]);
            }
        }
        tgt += SCAN_GRID;
        __syncthreads();
        if (tid == 0) {
            __threadfence();
            atomicAdd(&g_bar, 1);
            while (*(volatile int*)&g_bar < tgt) __nanosleep(64);
            __threadfence();
        }
        __syncthreads();
    }
}

// ----------------------------- misc kernels --------------------------------
__global__ void zero_k() { g_loss[0] = 0.0; g_loss[1] = 0.0; g_bar = 0; }

__global__ void loss1_k(const float* __restrict__ y, const float* __restrict__ x)
{
    __shared__ double sm[256];
    const int total = (TT - 1) * BSZ * FEAT;
    double s = 0.0;
    for (int idx = blockIdx.x * blockDim.x + threadIdx.x; idx < total;
         idx += gridDim.x * blockDim.x) {
        int f = idx & (FEAT - 1);
        int b = (idx >> 9) & (BSZ - 1);
        int t = idx >> 18;
        float d = y[idx] - x[(b * TTOT + t + 1) * FEAT + f];
        s += (double)d * (double)d;
    }
    sm[threadIdx.x] = s;
    __syncthreads();
    for (int o = 128; o > 0; o >>= 1) {
        if (threadIdx.x < o) sm[threadIdx.x] += sm[threadIdx.x + o];
        __syncthreads();
    }
    if (threadIdx.x == 0) atomicAdd(&g_loss[0], sm[0]);
}

__global__ void gather_k(const float* __restrict__ xall, const int* __restrict__ tt,
                         const float* __restrict__ x, float* __restrict__ out)
{
    __shared__ double sm[256];
    int idx = blockIdx.x * blockDim.x + threadIdx.x;
    int b = idx >> 9, f = idx & (FEAT - 1);
    int g = tt[b] - 1;
    float v = xall[(g * BSZ + b) * FEAT + f];
    out[idx] = v;
    float d = v - x[(b * TTOT + TTOT - 1) * FEAT + f];
    sm[threadIdx.x] = (double)d * (double)d;
    __syncthreads();
    for (int o = 128; o > 0; o >>= 1) {
        if (threadIdx.x < o) sm[threadIdx.x] += sm[threadIdx.x + o];
        __syncthreads();
    }
    if (threadIdx.x == 0) atomicAdd(&g_loss[1], sm[0]);
}

__global__ void fin_k(float* __restrict__ out)
{
    const double n1 = (double)(TT - 1) * BSZ * FEAT;
    const double n2 = (double)BSZ * FEAT;
    out[BSZ * FEAT] = (float)(g_loss[0] / (n1 * n1) + g_loss[1] / (n2 * n2));
}

// --------------------------- host orchestration ----------------------------
#define NOROW (1 << 30)

template<int MODE>
static void runtg(const float* A, const float* W, int K, const float* bias,
                  const float* gam, const float* rm,
                  const float* rv, const float* bet, float* C,
                  int M, int N, int rowDiv, int rowS1, int rowS2)
{
    dim3 grid((N + 63) / 64, M / 128);
    tgemm_k<MODE, 0><<<grid, 256>>>(A, W, K, nullptr, nullptr, 0,
                                    bias, nullptr, gam, rm, rv, bet,
                                    C, M, N, rowDiv, rowS1, rowS2);
}

extern "C" void kernel_launch(void* const* d_in, const int* in_sizes, int n_in,
                              void* d_out, int out_size)
{
    const float* x    = (const float*)d_in[0];
    const int*   tt   = (const int*)  d_in[1];
    const float* W_ih = (const float*)d_in[2];
    const float* W_hh = (const float*)d_in[3];
    const float* b_ih = (const float*)d_in[4];
    const float* b_hh = (const float*)d_in[5];
    const float* W1   = (const float*)d_in[6];
    const float* b1   = (const float*)d_in[7];
    const float* g1   = (const float*)d_in[8];
    const float* be1  = (const float*)d_in[9];
    const float* rm1  = (const float*)d_in[10];
    const float* rv1  = (const float*)d_in[11];
    const float* W2   = (const float*)d_in[12];
    const float* b2   = (const float*)d_in[13];
    const float* g2   = (const float*)d_in[14];
    const float* be2  = (const float*)d_in[15];
    const float* rm2  = (const float*)d_in[16];
    const float* rv2  = (const float*)d_in[17];
    const float* W3   = (const float*)d_in[18];
    const float* b3   = (const float*)d_in[19];
    const float* g3   = (const float*)d_in[20];
    const float* be3  = (const float*)d_in[21];
    const float* rm3  = (const float*)d_in[22];
    const float* rv3  = (const float*)d_in[23];
    float* out = (float*)d_out;

    float *prex, *hs, *z1, *z2, *y, *xall, *hA, *hB, *z1d, *z2d;
    cudaGetSymbolAddress((void**)&prex, g_prex);
    cudaGetSymbolAddress((void**)&hs,   g_hs);
    cudaGetSymbolAddress((void**)&z1,   g_z1);
    cudaGetSymbolAddress((void**)&z2,   g_z2);
    cudaGetSymbolAddress((void**)&y,    g_y);
    cudaGetSymbolAddress((void**)&xall, g_xall);
    cudaGetSymbolAddress((void**)&hA,   g_hA);
    cudaGetSymbolAddress((void**)&hB,   g_hB);
    cudaGetSymbolAddress((void**)&z1d,  g_z1d);
    cudaGetSymbolAddress((void**)&z2d,  g_z2d);

    const int BF   = BSZ * FEAT;
    const int BIGM = TT * BSZ;      // 32768

    static const int SCAN_SMEM = 512 * 68 * 4;   // 139264 B
    cudaFuncSetAttribute(scan_k, cudaFuncAttributeMaxDynamicSharedMemorySize,
                         SCAN_SMEM);

    zero_k<<<1, 1>>>();

    // 1. prex[t*B+b,:] = x[b,t,:] @ W_ih^T + b_ih   (tf32 tensor GEMM)
    runtg<0>(x, W_ih, FEAT, b_ih, nullptr, nullptr, nullptr, nullptr,
             prex, BIGM, FEAT, BSZ, FEAT, TTOT * FEAT);

    // 2. full RNN scan in ONE persistent kernel (fp32, W_hh in smem)
    scan_k<<<SCAN_GRID, 256, SCAN_SMEM>>>(prex, W_hh, b_hh, hs);

    // 3. autoencoder over all 32768 rows (tf32 tensor GEMMs)
    runtg<2>(hs, W1, FEAT, b1, g1, rm1, rv1, be1, z1, BIGM, HID,
             NOROW, 0, FEAT);
    runtg<2>(z1, W2, HID, b2, g2, rm2, rv2, be2, z2, BIGM, HID,
             NOROW, 0, HID);
    runtg<2>(z2, W3, HID, b3, g3, rm3, rv3, be3, y, BIGM, FEAT,
             NOROW, 0, HID);

    // 4. loss1
    loss1_k<<<2048, 256>>>(y, x);

    // 5. decode: 16 serial iterations, 4 tf32 tensor launches each
    const float* hprev = hs + (TT - 1) * BF;
    const float* xprev = y  + (TT - 1) * BF;
    for (int g = 0; g < GAPS; g++) {
        float* hcur = (g & 1) ? hB : hA;
        float* xcur = xall + g * BF;
        // h2 = tanh(x_hat@W_ih^T + h@W_hh^T + b_ih + b_hh)  — one dual GEMM
        tgemm_k<1, 1><<<dim3(FEAT / 64, BSZ / 128), 256>>>(
            xprev, W_ih, FEAT, hprev, W_hh, FEAT,
            b_ih, b_hh, nullptr, nullptr, nullptr, nullptr,
            hcur, BSZ, FEAT, NOROW, 0, FEAT);
        runtg<2>(hcur, W1, FEAT, b1, g1, rm1, rv1, be1, z1d, BSZ, HID,
                 NOROW, 0, FEAT);
        runtg<2>(z1d, W2, HID, b2, g2, rm2, rv2, be2, z2d, BSZ, HID,
                 NOROW, 0, HID);
        runtg<2>(z2d, W3, HID, b3, g3, rm3, rv3, be3, xcur, BSZ, FEAT,
                 NOROW, 0, HID);
        hprev = hcur;
        xprev = xcur;
    }

    // 6. gather x_pred + loss2, finalize scalar loss
    gather_k<<<BF / 256, 256>>>(xall, tt, x, out);
    if (out_size > BSZ * FEAT) fin_k<<<1, 1>>>(out);
}

// round 8
// speedup vs baseline: 2.3974x; 1.2294x over previous
#include <cuda_runtime.h>
#include <cuda_bf16.h>
#include <math.h>
#include <stdint.h>

// Problem constants
#define BSZ   512
#define TT    64          // used timesteps (T_TOTAL-1)
#define TTOT  65
#define FEAT  512
#define HID   1000
#define GAPS  16
#define EPSV  1e-5f
#define SCAN_GRID 128
#define NOROW (1 << 30)

// ---------------- scratch (device globals; allocation-free) ----------------
__device__ float g_prex[TT * BSZ * FEAT];
__device__ float g_hs  [TT * BSZ * FEAT];
__device__ float g_z1  [TT * BSZ * HID];
__device__ float g_z2  [TT * BSZ * HID];
__device__ float g_y   [TT * BSZ * FEAT];
__device__ float g_xall[GAPS * BSZ * FEAT];
__device__ float g_hA  [BSZ * FEAT];
__device__ float g_hB  [BSZ * FEAT];
__device__ float g_z1d [BSZ * HID];
__device__ float g_z2d [BSZ * HID];
// tf32-pre-rounded copies (so cp.async truncation-free into MMA)
__device__ float g_xr  [TTOT * BSZ * FEAT];
__device__ float g_wih [FEAT * FEAT];
__device__ float g_whh [FEAT * FEAT];
__device__ float g_w1  [HID * FEAT];
__device__ float g_w2  [HID * HID];
__device__ float g_w3  [FEAT * HID];
__device__ double g_loss[2];
__device__ int    g_bar;

// ---------------- tf32 helpers ----------------
__device__ __forceinline__ uint32_t f2tf(float f) {
    uint32_t u;
    asm("cvt.rna.tf32.f32 %0, %1;" : "=r"(u) : "f"(f));
    return u;
}
__device__ __forceinline__ float rndtf(float f) { return __uint_as_float(f2tf(f)); }

__device__ __forceinline__ void mma_tf32(float* c, const uint32_t* a,
                                         const uint32_t* b) {
    asm volatile(
        "mma.sync.aligned.m16n8k8.row.col.f32.tf32.tf32.f32 "
        "{%0,%1,%2,%3}, {%4,%5,%6,%7}, {%8,%9}, {%0,%1,%2,%3};"
        : "+f"(c[0]), "+f"(c[1]), "+f"(c[2]), "+f"(c[3])
        : "r"(a[0]), "r"(a[1]), "r"(a[2]), "r"(a[3]), "r"(b[0]), "r"(b[1]));
}
__device__ __forceinline__ void cpa16(uint32_t dst, const float* src, int sz) {
    asm volatile("cp.async.cg.shared.global [%0], [%1], 16, %2;"
                 :: "r"(dst), "l"(src), "r"(sz));
}

// ============ tf32 tensor GEMM, cp.async 3-stage pipeline ===================
// C = ep( A@W^T [+ A2@W2^T, same K] + bias )
// CTA tile 128(M) x 128(N) x 32(K); 8 warps = 4(m) x 2(n); warp tile 32x64.
// Inputs A/W/A2/W2 MUST already be tf32-rounded fp32 bit patterns.
// MODE 0: acc+bias   MODE 1: tanh(acc+bias+bias2)   MODE 2: BN epilogue
// All outputs are written tf32-rounded. M must be a multiple of 128.
template<int MODE, int DUAL>
__global__ void __launch_bounds__(256, 2) tgemm_k(
    const float* __restrict__ A,  const float* __restrict__ W,  int K,
    const float* __restrict__ A2, const float* __restrict__ W2,
    const float* __restrict__ bias, const float* __restrict__ bias2,
    const float* __restrict__ gam, const float* __restrict__ rm,
    const float* __restrict__ rv,  const float* __restrict__ bet,
    float* __restrict__ C, int M, int N,
    int rowDiv, int rowS1, int rowS2)
{
    extern __shared__ uint32_t smw[];   // 3 stages x (A 4096 + B 4096) words

    const int tid  = threadIdx.x;
    const int lane = tid & 31;
    const int warp = tid >> 5;
    const int gid  = lane >> 2;
    const int tg   = lane & 3;
    const int wm   = warp & 3;          // 4 m-warps (32 rows each)
    const int wn   = warp >> 2;         // 2 n-warps (64 cols each)
    const int bm0  = blockIdx.y * 128;
    const int bn0  = blockIdx.x * 128;
    const int swz  = gid << 2;

    const int KC1 = (K + 31) >> 5;
    const int KCT = DUAL ? 2 * KC1 : KC1;

    // per-thread loader constants
    long aoff0[4], boff[4];
    uint32_t dA[4];
    bool bvalid[4];
    const uint32_t smem0 = (uint32_t)__cvta_generic_to_shared(smw);
#pragma unroll
    for (int i = 0; i < 4; i++) {
        int idx = tid + i * 256;
        int r   = idx >> 3;
        int kq  = (idx & 7) * 4;
        int gm  = bm0 + r;
        aoff0[i] = (long)(gm / rowDiv) * rowS1 + (long)(gm % rowDiv) * rowS2 + kq;
        int gn = bn0 + r;
        bvalid[i] = gn < N;
        boff[i] = (long)(bvalid[i] ? gn : 0) * K + kq;
        dA[i] = smem0 + (uint32_t)(r * 32 + (kq ^ ((r & 7) << 2))) * 4;
    }

    auto issue = [&](int t) {
        uint32_t sb = (uint32_t)(t % 3) * 32768u;
        const float* Ap; const float* Wp; int k0; bool p0;
        if (!DUAL || t < KC1) { Ap = A;  Wp = W;  k0 = t << 5;         p0 = true; }
        else                  { Ap = A2; Wp = W2; k0 = (t - KC1) << 5; p0 = false; }
#pragma unroll
        for (int i = 0; i < 4; i++) {
            int idx = tid + i * 256;
            int r   = idx >> 3;
            int kq  = (idx & 7) * 4;
            int sz  = (k0 + kq + 3 < K) ? 16 : 0;
            long ao = p0 ? aoff0[i] : ((long)(bm0 + r) * K + kq);
            cpa16(dA[i] + sb,          Ap + ao + k0,      sz);
            cpa16(dA[i] + sb + 16384u, Wp + boff[i] + k0, bvalid[i] ? sz : 0);
        }
        asm volatile("cp.async.commit_group;");
    };

    float c[2][8][4];
#pragma unroll
    for (int i = 0; i < 2; i++)
#pragma unroll
        for (int j = 0; j < 8; j++)
#pragma unroll
            for (int r = 0; r < 4; r++) c[i][j][r] = 0.f;

    issue(0);
    issue(1);

    for (int t = 0; t < KCT; t++) {
        if (t == KCT - 1) asm volatile("cp.async.wait_group 0;");
        else              asm volatile("cp.async.wait_group 1;");
        __syncthreads();
        const uint32_t* Asb = smw + (t % 3) * 8192;
        const uint32_t* Bsb = Asb + 4096;
#pragma unroll
        for (int kt = 0; kt < 4; kt++) {
            const int klo = ((kt << 3) + tg) ^ swz;
            const int khi = klo ^ 4;
            uint32_t bfr[8][2];
#pragma unroll
            for (int nt = 0; nt < 8; nt++) {
                int nrow = (wn * 64 + nt * 8 + gid) << 5;
                bfr[nt][0] = Bsb[nrow + klo];
                bfr[nt][1] = Bsb[nrow + khi];
            }
            uint32_t afr[2][4];
#pragma unroll
            for (int mt = 0; mt < 2; mt++) {
                int mrow = (wm * 32 + mt * 16 + gid) << 5;
                afr[mt][0] = Asb[mrow + klo];
                afr[mt][1] = Asb[mrow + 256 + klo];
                afr[mt][2] = Asb[mrow + khi];
                afr[mt][3] = Asb[mrow + 256 + khi];
            }
#pragma unroll
            for (int mt = 0; mt < 2; mt++)
#pragma unroll
                for (int nt = 0; nt < 8; nt++)
                    mma_tf32(c[mt][nt], afr[mt], bfr[nt]);
        }
        __syncthreads();
        if (t + 2 < KCT) issue(t + 2);
    }

    // ---- epilogue (outputs tf32-rounded) ----
#pragma unroll
    for (int nt = 0; nt < 8; nt++) {
#pragma unroll
        for (int e = 0; e < 2; e++) {
            int col = bn0 + wn * 64 + nt * 8 + tg * 2 + e;
            if (col >= N) continue;
            float pb  = bias[col];
            float pb2 = (MODE == 1) ? bias2[col] : 0.f;
            float prm = 0.f, psc = 0.f, pbe = 0.f;
            if (MODE == 2) {
                prm = rm[col];
                psc = gam[col] * rsqrtf(rv[col] + EPSV);
                pbe = bet[col];
            }
#pragma unroll
            for (int mt = 0; mt < 2; mt++)
#pragma unroll
                for (int h = 0; h < 2; h++) {
                    int row = bm0 + wm * 32 + mt * 16 + gid + h * 8;
                    float v = c[mt][nt][h * 2 + e] + pb;
                    if (MODE == 1) v = tanhf(v + pb2);
                    if (MODE == 2) v = (v - prm) * psc + pbe;
                    C[(long)row * N + col] = rndtf(v);
                }
        }
    }
}

// ======================= persistent RNN scan kernel =========================
__global__ void __launch_bounds__(256) scan_k(const float* __restrict__ prex,
                                              const float* __restrict__ W_hh,
                                              const float* __restrict__ b_hh,
                                              float* __restrict__ hs)
{
    extern __shared__ float Wt[];             // [512][68]
    __shared__ float As[32][34];

    const int tid = threadIdx.x;
    const int nb  = blockIdx.x & 7;
    const int mb  = blockIdx.x >> 3;
    const int n0  = nb * 64;
    const int m0  = mb * 32;
    const int tx  = tid & 15;
    const int ty  = tid >> 4;

    for (int idx = tid; idx < 64 * 512; idx += 256) {
        int n = idx >> 9, k = idx & 511;
        Wt[k * 68 + n] = W_hh[(n0 + n) * FEAT + k];
    }
    float bh[4];
#pragma unroll
    for (int j = 0; j < 4; j++) bh[j] = b_hh[n0 + tx * 4 + j];
    __syncthreads();

    const int lrow = tid >> 3;
    const int lkc  = (tid & 7) * 4;

    int tgt = 0;
    for (int s = 0; s < TT; s++) {
        float acc[2][4];
#pragma unroll
        for (int i = 0; i < 2; i++)
#pragma unroll
            for (int j = 0; j < 4; j++) acc[i][j] = 0.f;

        if (s > 0) {
            const float* hp = hs + (size_t)(s - 1) * BSZ * FEAT;
            float4 v = *reinterpret_cast<const float4*>(
                hp + (m0 + lrow) * FEAT + lkc);
            for (int k0 = 0; k0 < FEAT; k0 += 32) {
                __syncthreads();
                As[lkc + 0][lrow] = v.x;
                As[lkc + 1][lrow] = v.y;
                As[lkc + 2][lrow] = v.z;
                As[lkc + 3][lrow] = v.w;
                __syncthreads();
                if (k0 + 32 < FEAT)
                    v = *reinterpret_cast<const float4*>(
                        hp + (m0 + lrow) * FEAT + k0 + 32 + lkc);
#pragma unroll
                for (int k = 0; k < 32; k++) {
                    float2 a = *reinterpret_cast<const float2*>(&As[k][ty * 2]);
                    float4 b = *reinterpret_cast<const float4*>(
                        &Wt[(k0 + k) * 68 + tx * 4]);
                    acc[0][0] = fmaf(a.x, b.x, acc[0][0]);
                    acc[0][1] = fmaf(a.x, b.y, acc[0][1]);
                    acc[0][2] = fmaf(a.x, b.z, acc[0][2]);
                    acc[0][3] = fmaf(a.x, b.w, acc[0][3]);
                    acc[1][0] = fmaf(a.y, b.x, acc[1][0]);
                    acc[1][1] = fmaf(a.y, b.y, acc[1][1]);
                    acc[1][2] = fmaf(a.y, b.z, acc[1][2]);
                    acc[1][3] = fmaf(a.y, b.w, acc[1][3]);
                }
            }
        }
        const float* px = prex + (size_t)s * BSZ * FEAT;
        float*       ho = hs   + (size_t)s * BSZ * FEAT;
#pragma unroll
        for (int i = 0; i < 2; i++) {
            int m = m0 + ty * 2 + i;
#pragma unroll
            for (int j = 0; j < 4; j++) {
                int n = n0 + tx * 4 + j;
                // write tf32-rounded so downstream GEMM cp.async is lossless
                ho[m * FEAT + n] =
                    rndtf(tanhf(acc[i][j] + px[m * FEAT + n] + bh[j]));
            }
        }
        tgt += SCAN_GRID;
        __syncthreads();
        if (tid == 0) {
            __threadfence();
            atomicAdd(&g_bar, 1);
            while (*(volatile int*)&g_bar < tgt) __nanosleep(64);
            __threadfence();
        }
        __syncthreads();
    }
}

// ----------------------------- misc kernels --------------------------------
__global__ void zero_k() { g_loss[0] = 0.0; g_loss[1] = 0.0; g_bar = 0; }

__global__ void round_k(const float* __restrict__ src, float* __restrict__ dst,
                        int n)
{
    for (int i = blockIdx.x * blockDim.x + threadIdx.x; i < n;
         i += gridDim.x * blockDim.x)
        dst[i] = rndtf(src[i]);
}

__global__ void loss1_k(const float* __restrict__ y, const float* __restrict__ x)
{
    __shared__ double sm[256];
    const int total = (TT - 1) * BSZ * FEAT;
    double s = 0.0;
    for (int idx = blockIdx.x * blockDim.x + threadIdx.x; idx < total;
         idx += gridDim.x * blockDim.x) {
        int f = idx & (FEAT - 1);
        int b = (idx >> 9) & (BSZ - 1);
        int t = idx >> 18;
        float d = y[idx] - x[(b * TTOT + t + 1) * FEAT + f];
        s += (double)d * (double)d;
    }
    sm[threadIdx.x] = s;
    __syncthreads();
    for (int o = 128; o > 0; o >>= 1) {
        if (threadIdx.x < o) sm[threadIdx.x] += sm[threadIdx.x + o];
        __syncthreads();
    }
    if (threadIdx.x == 0) atomicAdd(&g_loss[0], sm[0]);
}

__global__ void gather_k(const float* __restrict__ xall, const int* __restrict__ tt,
                         const float* __restrict__ x, float* __restrict__ out)
{
    __shared__ double sm[256];
    int idx = blockIdx.x * blockDim.x + threadIdx.x;
    int b = idx >> 9, f = idx & (FEAT - 1);
    int g = tt[b] - 1;
    float v = xall[(g * BSZ + b) * FEAT + f];
    out[idx] = v;
    float d = v - x[(b * TTOT + TTOT - 1) * FEAT + f];
    sm[threadIdx.x] = (double)d * (double)d;
    __syncthreads();
    for (int o = 128; o > 0; o >>= 1) {
        if (threadIdx.x < o) sm[threadIdx.x] += sm[threadIdx.x + o];
        __syncthreads();
    }
    if (threadIdx.x == 0) atomicAdd(&g_loss[1], sm[0]);
}

__global__ void fin_k(float* __restrict__ out)
{
    const double n1 = (double)(TT - 1) * BSZ * FEAT;
    const double n2 = (double)BSZ * FEAT;
    out[BSZ * FEAT] = (float)(g_loss[0] / (n1 * n1) + g_loss[1] / (n2 * n2));
}

// --------------------------- host orchestration ----------------------------
#define TG_SMEM 98304

template<int MODE>
static void runtg(const float* A, const float* W, int K, const float* bias,
                  const float* gam, const float* rm,
                  const float* rv, const float* bet, float* C,
                  int M, int N, int rowDiv, int rowS1, int rowS2)
{
    dim3 grid((N + 127) / 128, M / 128);
    tgemm_k<MODE, 0><<<grid, 256, TG_SMEM>>>(A, W, K, nullptr, nullptr,
                                             bias, nullptr, gam, rm, rv, bet,
                                             C, M, N, rowDiv, rowS1, rowS2);
}

extern "C" void kernel_launch(void* const* d_in, const int* in_sizes, int n_in,
                              void* d_out, int out_size)
{
    const float* x    = (const float*)d_in[0];
    const int*   tt   = (const int*)  d_in[1];
    const float* W_ih = (const float*)d_in[2];
    const float* W_hh = (const float*)d_in[3];
    const float* b_ih = (const float*)d_in[4];
    const float* b_hh = (const float*)d_in[5];
    const float* W1   = (const float*)d_in[6];
    const float* b1   = (const float*)d_in[7];
    const float* g1   = (const float*)d_in[8];
    const float* be1  = (const float*)d_in[9];
    const float* rm1  = (const float*)d_in[10];
    const float* rv1  = (const float*)d_in[11];
    const float* W2   = (const float*)d_in[12];
    const float* b2   = (const float*)d_in[13];
    const float* g2   = (const float*)d_in[14];
    const float* be2  = (const float*)d_in[15];
    const float* rm2  = (const float*)d_in[16];
    const float* rv2  = (const float*)d_in[17];
    const float* W3   = (const float*)d_in[18];
    const float* b3   = (const float*)d_in[19];
    const float* g3   = (const float*)d_in[20];
    const float* be3  = (const float*)d_in[21];
    const float* rm3  = (const float*)d_in[22];
    const float* rv3  = (const float*)d_in[23];
    float* out = (float*)d_out;

    float *prex, *hs, *z1, *z2, *y, *xall, *hA, *hB, *z1d, *z2d;
    float *xr, *wih, *whh, *w1, *w2, *w3;
    cudaGetSymbolAddress((void**)&prex, g_prex);
    cudaGetSymbolAddress((void**)&hs,   g_hs);
    cudaGetSymbolAddress((void**)&z1,   g_z1);
    cudaGetSymbolAddress((void**)&z2,   g_z2);
    cudaGetSymbolAddress((void**)&y,    g_y);
    cudaGetSymbolAddress((void**)&xall, g_xall);
    cudaGetSymbolAddress((void**)&hA,   g_hA);
    cudaGetSymbolAddress((void**)&hB,   g_hB);
    cudaGetSymbolAddress((void**)&z1d,  g_z1d);
    cudaGetSymbolAddress((void**)&z2d,  g_z2d);
    cudaGetSymbolAddress((void**)&xr,   g_xr);
    cudaGetSymbolAddress((void**)&wih,  g_wih);
    cudaGetSymbolAddress((void**)&whh,  g_whh);
    cudaGetSymbolAddress((void**)&w1,   g_w1);
    cudaGetSymbolAddress((void**)&w2,   g_w2);
    cudaGetSymbolAddress((void**)&w3,   g_w3);

    const int BF   = BSZ * FEAT;
    const int BIGM = TT * BSZ;      // 32768

    static const int SCAN_SMEM = 512 * 68 * 4;
    cudaFuncSetAttribute(scan_k, cudaFuncAttributeMaxDynamicSharedMemorySize,
                         SCAN_SMEM);
    cudaFuncSetAttribute(tgemm_k<0, 0>,
                         cudaFuncAttributeMaxDynamicSharedMemorySize, TG_SMEM);
    cudaFuncSetAttribute(tgemm_k<2, 0>,
                         cudaFuncAttributeMaxDynamicSharedMemorySize, TG_SMEM);
    cudaFuncSetAttribute(tgemm_k<1, 1>,
                         cudaFuncAttributeMaxDynamicSharedMemorySize, TG_SMEM);

    zero_k<<<1, 1>>>();

    // 0. pre-round GEMM inputs to tf32 (rna) once
    round_k<<<2048, 256>>>(x,    xr,  TTOT * BSZ * FEAT);
    round_k<<<256,  256>>>(W_ih, wih, FEAT * FEAT);
    round_k<<<256,  256>>>(W_hh, whh, FEAT * FEAT);
    round_k<<<512,  256>>>(W1,   w1,  HID * FEAT);
    round_k<<<1024, 256>>>(W2,   w2,  HID * HID);
    round_k<<<512,  256>>>(W3,   w3,  FEAT * HID);

    // 1. prex = x @ W_ih^T + b_ih
    runtg<0>(xr, wih, FEAT, b_ih, nullptr, nullptr, nullptr, nullptr,
             prex, BIGM, FEAT, BSZ, FEAT, TTOT * FEAT);

    // 2. full RNN scan (fp32 SIMT, W_hh resident in smem; tf32-rounded output)
    scan_k<<<SCAN_GRID, 256, SCAN_SMEM>>>(prex, W_hh, b_hh, hs);

    // 3. autoencoder over all 32768 rows
    runtg<2>(hs, w1, FEAT, b1, g1, rm1, rv1, be1, z1, BIGM, HID,
             NOROW, 0, FEAT);
    runtg<2>(z1, w2, HID, b2, g2, rm2, rv2, be2, z2, BIGM, HID,
             NOROW, 0, HID);
    runtg<2>(z2, w3, HID, b3, g3, rm3, rv3, be3, y, BIGM, FEAT,
             NOROW, 0, HID);

    // 4. loss1
    loss1_k<<<2048, 256>>>(y, x);

    // 5. decode: 16 serial iterations, 4 tensor GEMMs each
    const float* hprev = hs + (TT - 1) * BF;
    const float* xprev = y  + (TT - 1) * BF;
    for (int g = 0; g < GAPS; g++) {
        float* hcur = (g & 1) ? hB : hA;
        float* xcur = xall + g * BF;
        // h2 = tanh(x_hat@W_ih^T + h@W_hh^T + b_ih + b_hh) — dual-K GEMM
        tgemm_k<1, 1><<<dim3(FEAT / 128, BSZ / 128), 256, TG_SMEM>>>(
            xprev, wih, FEAT, hprev, whh,
            b_ih, b_hh, nullptr, nullptr, nullptr, nullptr,
            hcur, BSZ, FEAT, NOROW, 0, FEAT);
        runtg<2>(hcur, w1, FEAT, b1, g1, rm1, rv1, be1, z1d, BSZ, HID,
                 NOROW, 0, FEAT);
        runtg<2>(z1d, w2, HID, b2, g2, rm2, rv2, be2, z2d, BSZ, HID,
                 NOROW, 0, HID);
        runtg<2>(z2d, w3, HID, b3, g3, rm3, rv3, be3, xcur, BSZ, FEAT,
                 NOROW, 0, HID);
        hprev = hcur;
        xprev = xcur;
    }

    // 6. gather x_pred + loss2, finalize scalar loss
    gather_k<<<BF / 256, 256>>>(xall, tt, x, out);
    if (out_size > BSZ * FEAT) fin_k<<<1, 1>>>(out);
}

// round 9
// speedup vs baseline: 2.7020x; 1.1271x over previous
#include <cuda_runtime.h>
#include <cuda_bf16.h>
#include <math.h>
#include <stdint.h>

// Problem constants
#define BSZ   512
#define TT    64          // used timesteps (T_TOTAL-1)
#define TTOT  65
#define FEAT  512
#define HID   1000
#define GAPS  16
#define EPSV  1e-5f
#define SCAN_GRID 128
#define NOROW (1 << 30)

// ---------------- scratch (device globals; allocation-free) ----------------
__device__ float g_prex[TT * BSZ * FEAT];
__device__ float g_hs  [TT * BSZ * FEAT];
__device__ float g_z1  [TT * BSZ * HID];
__device__ float g_z2  [TT * BSZ * HID];
__device__ float g_y   [TT * BSZ * FEAT];
__device__ float g_xall[GAPS * BSZ * FEAT];
__device__ float g_hA  [BSZ * FEAT];
__device__ float g_hB  [BSZ * FEAT];
__device__ float g_z1d [BSZ * HID];
__device__ float g_z2d [BSZ * HID];
// tf32-pre-rounded copies
__device__ float g_xr  [TTOT * BSZ * FEAT];
__device__ float g_wih [FEAT * FEAT];
__device__ float g_whh [FEAT * FEAT];
__device__ float g_w1  [HID * FEAT];
__device__ float g_w2  [HID * HID];
__device__ float g_w3  [FEAT * HID];
__device__ double g_loss[2];
__device__ int    g_bar;

// ---------------- tf32 helpers ----------------
__device__ __forceinline__ uint32_t f2tf(float f) {
    uint32_t u;
    asm("cvt.rna.tf32.f32 %0, %1;" : "=r"(u) : "f"(f));
    return u;
}
__device__ __forceinline__ float rndtf(float f) { return __uint_as_float(f2tf(f)); }

__device__ __forceinline__ void mma_tf32(float* c, const uint32_t* a,
                                         const uint32_t* b) {
    asm volatile(
        "mma.sync.aligned.m16n8k8.row.col.f32.tf32.tf32.f32 "
        "{%0,%1,%2,%3}, {%4,%5,%6,%7}, {%8,%9}, {%0,%1,%2,%3};"
        : "+f"(c[0]), "+f"(c[1]), "+f"(c[2]), "+f"(c[3])
        : "r"(a[0]), "r"(a[1]), "r"(a[2]), "r"(a[3]), "r"(b[0]), "r"(b[1]));
}
__device__ __forceinline__ void cpa16(uint32_t dst, const float* src, int sz) {
    asm volatile("cp.async.cg.shared.global [%0], [%1], 16, %2;"
                 :: "r"(dst), "l"(src), "r"(sz));
}

// ============ tf32 tensor GEMM, cp.async 3-stage pipeline ===================
// C = ep( A@W^T [+ A2@W2^T, same K] + bias )
// CTA tile 128x128x32; 8 warps = 4(m) x 2(n); warp tile 32x64.
// Inputs MUST be tf32-rounded. Outputs written tf32-rounded. M % 128 == 0.
template<int MODE, int DUAL>
__global__ void __launch_bounds__(256, 2) tgemm_k(
    const float* __restrict__ A,  const float* __restrict__ W,  int K,
    const float* __restrict__ A2, const float* __restrict__ W2,
    const float* __restrict__ bias, const float* __restrict__ bias2,
    const float* __restrict__ gam, const float* __restrict__ rm,
    const float* __restrict__ rv,  const float* __restrict__ bet,
    float* __restrict__ C, int M, int N,
    int rowDiv, int rowS1, int rowS2)
{
    extern __shared__ uint32_t smw[];   // 3 stages x (A 4096 + B 4096) words

    const int tid  = threadIdx.x;
    const int lane = tid & 31;
    const int warp = tid >> 5;
    const int gid  = lane >> 2;
    const int tg   = lane & 3;
    const int wm   = warp & 3;
    const int wn   = warp >> 2;
    const int bm0  = blockIdx.y * 128;
    const int bn0  = blockIdx.x * 128;
    const int swz  = gid << 2;

    const int KC1 = (K + 31) >> 5;
    const int KCT = DUAL ? 2 * KC1 : KC1;

    long aoff0[4], boff[4];
    uint32_t dA[4];
    bool bvalid[4];
    const uint32_t smem0 = (uint32_t)__cvta_generic_to_shared(smw);
#pragma unroll
    for (int i = 0; i < 4; i++) {
        int idx = tid + i * 256;
        int r   = idx >> 3;
        int kq  = (idx & 7) * 4;
        int gm  = bm0 + r;
        aoff0[i] = (long)(gm / rowDiv) * rowS1 + (long)(gm % rowDiv) * rowS2 + kq;
        int gn = bn0 + r;
        bvalid[i] = gn < N;
        boff[i] = (long)(bvalid[i] ? gn : 0) * K + kq;
        dA[i] = smem0 + (uint32_t)(r * 32 + (kq ^ ((r & 7) << 2))) * 4;
    }

    auto issue = [&](int t) {
        uint32_t sb = (uint32_t)(t % 3) * 32768u;
        const float* Ap; const float* Wp; int k0; bool p0;
        if (!DUAL || t < KC1) { Ap = A;  Wp = W;  k0 = t << 5;         p0 = true; }
        else                  { Ap = A2; Wp = W2; k0 = (t - KC1) << 5; p0 = false; }
#pragma unroll
        for (int i = 0; i < 4; i++) {
            int idx = tid + i * 256;
            int r   = idx >> 3;
            int kq  = (idx & 7) * 4;
            int sz  = (k0 + kq + 3 < K) ? 16 : 0;
            long ao = p0 ? aoff0[i] : ((long)(bm0 + r) * K + kq);
            cpa16(dA[i] + sb,          Ap + ao + k0,      sz);
            cpa16(dA[i] + sb + 16384u, Wp + boff[i] + k0, bvalid[i] ? sz : 0);
        }
        asm volatile("cp.async.commit_group;");
    };

    float c[2][8][4];
#pragma unroll
    for (int i = 0; i < 2; i++)
#pragma unroll
        for (int j = 0; j < 8; j++)
#pragma unroll
            for (int r = 0; r < 4; r++) c[i][j][r] = 0.f;

    issue(0);
    issue(1);

    for (int t = 0; t < KCT; t++) {
        if (t == KCT - 1) asm volatile("cp.async.wait_group 0;");
        else              asm volatile("cp.async.wait_group 1;");
        __syncthreads();
        const uint32_t* Asb = smw + (t % 3) * 8192;
        const uint32_t* Bsb = Asb + 4096;
#pragma unroll
        for (int kt = 0; kt < 4; kt++) {
            const int klo = ((kt << 3) + tg) ^ swz;
            const int khi = klo ^ 4;
            uint32_t bfr[8][2];
#pragma unroll
            for (int nt = 0; nt < 8; nt++) {
                int nrow = (wn * 64 + nt * 8 + gid) << 5;
                bfr[nt][0] = Bsb[nrow + klo];
                bfr[nt][1] = Bsb[nrow + khi];
            }
            uint32_t afr[2][4];
#pragma unroll
            for (int mt = 0; mt < 2; mt++) {
                int mrow = (wm * 32 + mt * 16 + gid) << 5;
                afr[mt][0] = Asb[mrow + klo];
                afr[mt][1] = Asb[mrow + 256 + klo];
                afr[mt][2] = Asb[mrow + khi];
                afr[mt][3] = Asb[mrow + 256 + khi];
            }
#pragma unroll
            for (int mt = 0; mt < 2; mt++)
#pragma unroll
                for (int nt = 0; nt < 8; nt++)
                    mma_tf32(c[mt][nt], afr[mt], bfr[nt]);
        }
        __syncthreads();
        if (t + 2 < KCT) issue(t + 2);
    }

#pragma unroll
    for (int nt = 0; nt < 8; nt++) {
#pragma unroll
        for (int e = 0; e < 2; e++) {
            int col = bn0 + wn * 64 + nt * 8 + tg * 2 + e;
            if (col >= N) continue;
            float pb  = bias[col];
            float pb2 = (MODE == 1) ? bias2[col] : 0.f;
            float prm = 0.f, psc = 0.f, pbe = 0.f;
            if (MODE == 2) {
                prm = rm[col];
                psc = gam[col] * rsqrtf(rv[col] + EPSV);
                pbe = bet[col];
            }
#pragma unroll
            for (int mt = 0; mt < 2; mt++)
#pragma unroll
                for (int h = 0; h < 2; h++) {
                    int row = bm0 + wm * 32 + mt * 16 + gid + h * 8;
                    float v = c[mt][nt][h * 2 + e] + pb;
                    if (MODE == 1) v = tanhf(v + pb2);
                    if (MODE == 2) v = (v - prm) * psc + pbe;
                    C[(long)row * N + col] = rndtf(v);
                }
        }
    }
}

// ============== persistent TENSOR-CORE RNN scan =============================
// 128 CTAs: mb = bid>>4 (8 tiles of 64 batch rows), nb = bid&15 (16 tiles of
// 32 features). W_hh slice [32 x 512] (tf32, swizzled) resident in smem.
// Per step: h[s-1] 64x512 tile streamed in 16 double-buffered cp.async chunks.
// 8 warps = 4(m) x 2(n), warp tile 16x16.
__global__ void __launch_bounds__(256) scan_k(const float* __restrict__ prex,
                                              const float* __restrict__ whh,
                                              const float* __restrict__ b_hh,
                                              float* __restrict__ hs)
{
    extern __shared__ uint32_t sm[];
    uint32_t* Wt  = sm;            // 32*512 words = 64 KB
    uint32_t* Ad  = sm + 16384;    // 2 x 64x32 words = 16 KB

    const int tid  = threadIdx.x;
    const int lane = tid & 31;
    const int warp = tid >> 5;
    const int gid  = lane >> 2;
    const int tg   = lane & 3;
    const int wm   = warp & 3;     // 4 m-warps (16 rows each)
    const int wn   = warp >> 2;    // 2 n-warps (16 cols each)
    const int nb   = blockIdx.x & 15;
    const int mb   = blockIdx.x >> 4;
    const int n0   = nb * 32;
    const int m0   = mb * 64;
    const int swz  = gid << 2;

    // load W slice: Wt[n][k], swizzle within each 32-word chunk
    for (int idx = tid; idx < 32 * 512; idx += 256) {
        int n = idx >> 9, k = idx & 511;
        Wt[n * 512 + (k & ~31) + ((k & 31) ^ ((n & 7) << 2))] =
            __float_as_uint(whh[(n0 + n) * FEAT + k]);
    }

    // A-chunk loader constants: 2 float4 per thread per chunk
    const uint32_t smemA = (uint32_t)__cvta_generic_to_shared(Ad);
    uint32_t dA[2];
    int arow[2], akq[2];
#pragma unroll
    for (int i = 0; i < 2; i++) {
        int idx = tid + i * 256;
        arow[i] = idx >> 3;            // 0..63
        akq[i]  = (idx & 7) * 4;
        dA[i] = smemA + (uint32_t)(arow[i] * 32 + (akq[i] ^ ((arow[i] & 7) << 2))) * 4;
    }
    __syncthreads();

    int tgt = 0;
    for (int s = 0; s < TT; s++) {
        float c[2][4];
#pragma unroll
        for (int j = 0; j < 2; j++)
#pragma unroll
            for (int r = 0; r < 4; r++) c[j][r] = 0.f;

        if (s > 0) {
            const float* hp = hs + (size_t)(s - 1) * BSZ * FEAT;
            auto issueA = [&](int ch) {
                uint32_t sb = (uint32_t)(ch & 1) * 8192u;
#pragma unroll
                for (int i = 0; i < 2; i++)
                    cpa16(dA[i] + sb,
                          hp + (m0 + arow[i]) * FEAT + ch * 32 + akq[i], 16);
                asm volatile("cp.async.commit_group;");
            };
            issueA(0);
            issueA(1);
            for (int ch = 0; ch < 16; ch++) {
                if (ch == 15) asm volatile("cp.async.wait_group 0;");
                else          asm volatile("cp.async.wait_group 1;");
                __syncthreads();
                const uint32_t* Asb = Ad + (ch & 1) * 2048;
                const uint32_t* Wc  = Wt + ch * 32;
#pragma unroll
                for (int kt = 0; kt < 4; kt++) {
                    const int klo = ((kt << 3) + tg) ^ swz;
                    const int khi = klo ^ 4;
                    uint32_t afr[4];
                    int mrow = (wm * 16 + gid) << 5;
                    afr[0] = Asb[mrow + klo];
                    afr[1] = Asb[mrow + 256 + klo];
                    afr[2] = Asb[mrow + khi];
                    afr[3] = Asb[mrow + 256 + khi];
#pragma unroll
                    for (int nt = 0; nt < 2; nt++) {
                        int nrow = (wn * 16 + nt * 8 + gid) << 9;
                        uint32_t bfr[2];
                        bfr[0] = Wc[nrow + klo];
                        bfr[1] = Wc[nrow + khi];
                        mma_tf32(c[nt], afr, bfr);
                    }
                }
                __syncthreads();
                if (ch + 2 < 16) issueA(ch + 2);
            }
        }
        // epilogue: h_s = rndtf(tanh(acc + prex_s + b_hh))
        const float* px = prex + (size_t)s * BSZ * FEAT;
        float*       ho = hs   + (size_t)s * BSZ * FEAT;
#pragma unroll
        for (int nt = 0; nt < 2; nt++) {
            int col = n0 + wn * 16 + nt * 8 + tg * 2;
            float b0 = b_hh[col], b1 = b_hh[col + 1];
#pragma unroll
            for (int h = 0; h < 2; h++) {
                int row = m0 + wm * 16 + gid + h * 8;
                const float2 p = *reinterpret_cast<const float2*>(
                    px + (size_t)row * FEAT + col);
                float2 o;
                o.x = rndtf(tanhf(c[nt][h * 2 + 0] + p.x + b0));
                o.y = rndtf(tanhf(c[nt][h * 2 + 1] + p.y + b1));
                *reinterpret_cast<float2*>(ho + (size_t)row * FEAT + col) = o;
            }
        }
        // grid barrier
        tgt += SCAN_GRID;
        __syncthreads();
        if (tid == 0) {
            __threadfence();
            atomicAdd(&g_bar, 1);
            while (*(volatile int*)&g_bar < tgt) __nanosleep(64);
            __threadfence();
        }
        __syncthreads();
    }
}

// ----------------------------- misc kernels --------------------------------
__global__ void zero_k() { g_loss[0] = 0.0; g_loss[1] = 0.0; g_bar = 0; }

__global__ void round_k(const float* __restrict__ src, float* __restrict__ dst,
                        int n)
{
    for (int i = blockIdx.x * blockDim.x + threadIdx.x; i < n;
         i += gridDim.x * blockDim.x)
        dst[i] = rndtf(src[i]);
}

__global__ void loss1_k(const float* __restrict__ y, const float* __restrict__ x)
{
    __shared__ double sm[256];
    const int total = (TT - 1) * BSZ * FEAT;
    double s = 0.0;
    for (int idx = blockIdx.x * blockDim.x + threadIdx.x; idx < total;
         idx += gridDim.x * blockDim.x) {
        int f = idx & (FEAT - 1);
        int b = (idx >> 9) & (BSZ - 1);
        int t = idx >> 18;
        float d = y[idx] - x[(b * TTOT + t + 1) * FEAT + f];
        s += (double)d * (double)d;
    }
    sm[threadIdx.x] = s;
    __syncthreads();
    for (int o = 128; o > 0; o >>= 1) {
        if (threadIdx.x < o) sm[threadIdx.x] += sm[threadIdx.x + o];
        __syncthreads();
    }
    if (threadIdx.x == 0) atomicAdd(&g_loss[0], sm[0]);
}

__global__ void gather_k(const float* __restrict__ xall, const int* __restrict__ tt,
                         const float* __restrict__ x, float* __restrict__ out)
{
    __shared__ double sm[256];
    int idx = blockIdx.x * blockDim.x + threadIdx.x;
    int b = idx >> 9, f = idx & (FEAT - 1);
    int g = tt[b] - 1;
    float v = xall[(g * BSZ + b) * FEAT + f];
    out[idx] = v;
    float d = v - x[(b * TTOT + TTOT - 1) * FEAT + f];
    sm[threadIdx.x] = (double)d * (double)d;
    __syncthreads();
    for (int o = 128; o > 0; o >>= 1) {
        if (threadIdx.x < o) sm[threadIdx.x] += sm[threadIdx.x + o];
        __syncthreads();
    }
    if (threadIdx.x == 0) atomicAdd(&g_loss[1], sm[0]);
}

__global__ void fin_k(float* __restrict__ out)
{
    const double n1 = (double)(TT - 1) * BSZ * FEAT;
    const double n2 = (double)BSZ * FEAT;
    out[BSZ * FEAT] = (float)(g_loss[0] / (n1 * n1) + g_loss[1] / (n2 * n2));
}

// --------------------------- host orchestration ----------------------------
#define TG_SMEM 98304
#define SC_SMEM (16384 * 4 + 4096 * 4)   // 64 KB W + 16 KB A = 81920

template<int MODE>
static void runtg(const float* A, const float* W, int K, const float* bias,
                  const float* gam, const float* rm,
                  const float* rv, const float* bet, float* C,
                  int M, int N, int rowDiv, int rowS1, int rowS2)
{
    dim3 grid((N + 127) / 128, M / 128);
    tgemm_k<MODE, 0><<<grid, 256, TG_SMEM>>>(A, W, K, nullptr, nullptr,
                                             bias, nullptr, gam, rm, rv, bet,
                                             C, M, N, rowDiv, rowS1, rowS2);
}

extern "C" void kernel_launch(void* const* d_in, const int* in_sizes, int n_in,
                              void* d_out, int out_size)
{
    const float* x    = (const float*)d_in[0];
    const int*   tt   = (const int*)  d_in[1];
    const float* W_ih = (const float*)d_in[2];
    const float* W_hh = (const float*)d_in[3];
    const float* b_ih = (const float*)d_in[4];
    const float* b_hh = (const float*)d_in[5];
    const float* W1   = (const float*)d_in[6];
    const float* b1   = (const float*)d_in[7];
    const float* g1   = (const float*)d_in[8];
    const float* be1  = (const float*)d_in[9];
    const float* rm1  = (const float*)d_in[10];
    const float* rv1  = (const float*)d_in[11];
    const float* W2   = (const float*)d_in[12];
    const float* b2   = (const float*)d_in[13];
    const float* g2   = (const float*)d_in[14];
    const float* be2  = (const float*)d_in[15];
    const float* rm2  = (const float*)d_in[16];
    const float* rv2  = (const float*)d_in[17];
    const float* W3   = (const float*)d_in[18];
    const float* b3   = (const float*)d_in[19];
    const float* g3   = (const float*)d_in[20];
    const float* be3  = (const float*)d_in[21];
    const float* rm3  = (const float*)d_in[22];
    const float* rv3  = (const float*)d_in[23];
    float* out = (float*)d_out;

    float *prex, *hs, *z1, *z2, *y, *xall, *hA, *hB, *z1d, *z2d;
    float *xr, *wih, *whh, *w1, *w2, *w3;
    cudaGetSymbolAddress((void**)&prex, g_prex);
    cudaGetSymbolAddress((void**)&hs,   g_hs);
    cudaGetSymbolAddress((void**)&z1,   g_z1);
    cudaGetSymbolAddress((void**)&z2,   g_z2);
    cudaGetSymbolAddress((void**)&y,    g_y);
    cudaGetSymbolAddress((void**)&xall, g_xall);
    cudaGetSymbolAddress((void**)&hA,   g_hA);
    cudaGetSymbolAddress((void**)&hB,   g_hB);
    cudaGetSymbolAddress((void**)&z1d,  g_z1d);
    cudaGetSymbolAddress((void**)&z2d,  g_z2d);
    cudaGetSymbolAddress((void**)&xr,   g_xr);
    cudaGetSymbolAddress((void**)&wih,  g_wih);
    cudaGetSymbolAddress((void**)&whh,  g_whh);
    cudaGetSymbolAddress((void**)&w1,   g_w1);
    cudaGetSymbolAddress((void**)&w2,   g_w2);
    cudaGetSymbolAddress((void**)&w3,   g_w3);

    const int BF   = BSZ * FEAT;
    const int BIGM = TT * BSZ;

    cudaFuncSetAttribute(scan_k, cudaFuncAttributeMaxDynamicSharedMemorySize,
                         SC_SMEM);
    cudaFuncSetAttribute(tgemm_k<0, 0>,
                         cudaFuncAttributeMaxDynamicSharedMemorySize, TG_SMEM);
    cudaFuncSetAttribute(tgemm_k<2, 0>,
                         cudaFuncAttributeMaxDynamicSharedMemorySize, TG_SMEM);
    cudaFuncSetAttribute(tgemm_k<1, 1>,
                         cudaFuncAttributeMaxDynamicSharedMemorySize, TG_SMEM);

    zero_k<<<1, 1>>>();

    // 0. pre-round GEMM inputs to tf32 (rna) once
    round_k<<<2048, 256>>>(x,    xr,  TTOT * BSZ * FEAT);
    round_k<<<256,  256>>>(W_ih, wih, FEAT * FEAT);
    round_k<<<256,  256>>>(W_hh, whh, FEAT * FEAT);
    round_k<<<512,  256>>>(W1,   w1,  HID * FEAT);
    round_k<<<1024, 256>>>(W2,   w2,  HID * HID);
    round_k<<<512,  256>>>(W3,   w3,  FEAT * HID);

    // 1. prex = x @ W_ih^T + b_ih
    runtg<0>(xr, wih, FEAT, b_ih, nullptr, nullptr, nullptr, nullptr,
             prex, BIGM, FEAT, BSZ, FEAT, TTOT * FEAT);

    // 2. full RNN scan — persistent TENSOR-CORE kernel
    scan_k<<<SCAN_GRID, 256, SC_SMEM>>>(prex, whh, b_hh, hs);

    // 3. autoencoder over all 32768 rows
    runtg<2>(hs, w1, FEAT, b1, g1, rm1, rv1, be1, z1, BIGM, HID,
             NOROW, 0, FEAT);
    runtg<2>(z1, w2, HID, b2, g2, rm2, rv2, be2, z2, BIGM, HID,
             NOROW, 0, HID);
    runtg<2>(z2, w3, HID, b3, g3, rm3, rv3, be3, y, BIGM, FEAT,
             NOROW, 0, HID);

    // 4. loss1
    loss1_k<<<2048, 256>>>(y, x);

    // 5. decode: 16 serial iterations, 4 tensor GEMMs each
    const float* hprev = hs + (TT - 1) * BF;
    const float* xprev = y  + (TT - 1) * BF;
    for (int g = 0; g < GAPS; g++) {
        float* hcur = (g & 1) ? hB : hA;
        float* xcur = xall + g * BF;
        tgemm_k<1, 1><<<dim3(FEAT / 128, BSZ / 128), 256, TG_SMEM>>>(
            xprev, wih, FEAT, hprev, whh,
            b_ih, b_hh, nullptr, nullptr, nullptr, nullptr,
            hcur, BSZ, FEAT, NOROW, 0, FEAT);
        runtg<2>(hcur, w1, FEAT, b1, g1, rm1, rv1, be1, z1d, BSZ, HID,
                 NOROW, 0, FEAT);
        runtg<2>(z1d, w2, HID, b2, g2, rm2, rv2, be2, z2d, BSZ, HID,
                 NOROW, 0, HID);
        runtg<2>(z2d, w3, HID, b3, g3, rm3, rv3, be3, xcur, BSZ, FEAT,
                 NOROW, 0, HID);
        hprev = hcur;
        xprev = xcur;
    }

    // 6. gather x_pred + loss2, finalize scalar loss
    gather_k<<<BF / 256, 256>>>(xall, tt, x, out);
    if (out_size > BSZ * FEAT) fin_k<<<1, 1>>>(out);
}

// round 14
// speedup vs baseline: 4.0552x; 1.5008x over previous
#include <cuda_runtime.h>
#include <cuda_bf16.h>
#include <math.h>
#include <stdint.h>

// Problem constants
#define BSZ   512
#define TT    64          // used timesteps (T_TOTAL-1)
#define TTOT  65
#define FEAT  512
#define HID   1000
#define GAPS  16
#define EPSV  1e-5f
#define SCAN_GRID 128
#define NOROW (1 << 30)

// ---------------- scratch (device globals; allocation-free) ----------------
__device__ float g_prex[TT * BSZ * FEAT];
__device__ float g_hs  [TT * BSZ * FEAT];
__device__ float g_z1  [TT * BSZ * HID];
__device__ float g_z2  [TT * BSZ * HID];
__device__ float g_y   [TT * BSZ * FEAT];
__device__ float g_xall[GAPS * BSZ * FEAT];
__device__ float g_hA  [BSZ * FEAT];
__device__ float g_hB  [BSZ * FEAT];
__device__ float g_z1d [BSZ * HID];
__device__ float g_z2d [BSZ * HID];
// tf32-pre-rounded copies
__device__ float g_xr  [TTOT * BSZ * FEAT];
__device__ float g_wih [FEAT * FEAT];
__device__ float g_whh [FEAT * FEAT];
__device__ float g_w1  [HID * FEAT];
__device__ float g_w2  [HID * HID];
__device__ float g_w3  [FEAT * HID];
__device__ double g_loss[2];
__device__ int    g_bar;

// ---------------- tf32 helpers ----------------
__device__ __forceinline__ uint32_t f2tf(float f) {
    uint32_t u;
    asm("cvt.rna.tf32.f32 %0, %1;" : "=r"(u) : "f"(f));
    return u;
}
__device__ __forceinline__ float rndtf(float f) { return __uint_as_float(f2tf(f)); }

__device__ __forceinline__ void mma_tf32(float* c, const uint32_t* a,
                                         const uint32_t* b) {
    asm volatile(
        "mma.sync.aligned.m16n8k8.row.col.f32.tf32.tf32.f32 "
        "{%0,%1,%2,%3}, {%4,%5,%6,%7}, {%8,%9}, {%0,%1,%2,%3};"
        : "+f"(c[0]), "+f"(c[1]), "+f"(c[2]), "+f"(c[3])
        : "r"(a[0]), "r"(a[1]), "r"(a[2]), "r"(a[3]), "r"(b[0]), "r"(b[1]));
}
__device__ __forceinline__ void cpa16(uint32_t dst, const float* src, int sz) {
    asm volatile("cp.async.cg.shared.global [%0], [%1], 16, %2;"
                 :: "r"(dst), "l"(src), "r"(sz));
}

// ============ tf32 tensor GEMM, cp.async 3-stage, 128x128 tile ==============
// C = ep( A@W^T [+ A2@W2^T, same K] + bias )
// 8 warps = 4(m) x 2(n); warp tile 32x64. Inputs tf32-rounded; M % 128 == 0.
template<int MODE, int DUAL>
__global__ void __launch_bounds__(256, 2) tgemm_k(
    const float* __restrict__ A,  const float* __restrict__ W,  int K,
    const float* __restrict__ A2, const float* __restrict__ W2,
    const float* __restrict__ bias, const float* __restrict__ bias2,
    const float* __restrict__ gam, const float* __restrict__ rm,
    const float* __restrict__ rv,  const float* __restrict__ bet,
    float* __restrict__ C, int M, int N,
    int rowDiv, int rowS1, int rowS2)
{
    extern __shared__ uint32_t smw[];   // 3 stages x (A 4096 + B 4096) words

    const int tid  = threadIdx.x;
    const int lane = tid & 31;
    const int warp = tid >> 5;
    const int gid  = lane >> 2;
    const int tg   = lane & 3;
    const int wm   = warp & 3;
    const int wn   = warp >> 2;
    const int bm0  = blockIdx.y * 128;
    const int bn0  = blockIdx.x * 128;
    const int swz  = gid << 2;

    const int KC1 = (K + 31) >> 5;
    const int KCT = DUAL ? 2 * KC1 : KC1;

    long aoff0[4], boff[4];
    uint32_t dA[4];
    bool bvalid[4];
    const uint32_t smem0 = (uint32_t)__cvta_generic_to_shared(smw);
#pragma unroll
    for (int i = 0; i < 4; i++) {
        int idx = tid + i * 256;
        int r   = idx >> 3;
        int kq  = (idx & 7) * 4;
        int gm  = bm0 + r;
        aoff0[i] = (long)(gm / rowDiv) * rowS1 + (long)(gm % rowDiv) * rowS2 + kq;
        int gn = bn0 + r;
        bvalid[i] = gn < N;
        boff[i] = (long)(bvalid[i] ? gn : 0) * K + kq;
        dA[i] = smem0 + (uint32_t)(r * 32 + (kq ^ ((r & 7) << 2))) * 4;
    }

    auto issue = [&](int t) {
        uint32_t sb = (uint32_t)(t % 3) * 32768u;
        const float* Ap; const float* Wp; int k0; bool p0;
        if (!DUAL || t < KC1) { Ap = A;  Wp = W;  k0 = t << 5;         p0 = true; }
        else                  { Ap = A2; Wp = W2; k0 = (t - KC1) << 5; p0 = false; }
#pragma unroll
        for (int i = 0; i < 4; i++) {
            int idx = tid + i * 256;
            int r   = idx >> 3;
            int kq  = (idx & 7) * 4;
            int sz  = (k0 + kq + 3 < K) ? 16 : 0;
            long ao = p0 ? aoff0[i] : ((long)(bm0 + r) * K + kq);
            cpa16(dA[i] + sb,          Ap + ao + k0,      sz);
            cpa16(dA[i] + sb + 16384u, Wp + boff[i] + k0, bvalid[i] ? sz : 0);
        }
        asm volatile("cp.async.commit_group;");
    };

    float c[2][8][4];
#pragma unroll
    for (int i = 0; i < 2; i++)
#pragma unroll
        for (int j = 0; j < 8; j++)
#pragma unroll
            for (int r = 0; r < 4; r++) c[i][j][r] = 0.f;

    issue(0);
    issue(1);

    for (int t = 0; t < KCT; t++) {
        if (t == KCT - 1) asm volatile("cp.async.wait_group 0;");
        else              asm volatile("cp.async.wait_group 1;");
        __syncthreads();
        const uint32_t* Asb = smw + (t % 3) * 8192;
        const uint32_t* Bsb = Asb + 4096;
#pragma unroll
        for (int kt = 0; kt < 4; kt++) {
            const int klo = ((kt << 3) + tg) ^ swz;
            const int khi = klo ^ 4;
            uint32_t bfr[8][2];
#pragma unroll
            for (int nt = 0; nt < 8; nt++) {
                int nrow = (wn * 64 + nt * 8 + gid) << 5;
                bfr[nt][0] = Bsb[nrow + klo];
                bfr[nt][1] = Bsb[nrow + khi];
            }
            uint32_t afr[2][4];
#pragma unroll
            for (int mt = 0; mt < 2; mt++) {
                int mrow = (wm * 32 + mt * 16 + gid) << 5;
                afr[mt][0] = Asb[mrow + klo];
                afr[mt][1] = Asb[mrow + 256 + klo];
                afr[mt][2] = Asb[mrow + khi];
                afr[mt][3] = Asb[mrow + 256 + khi];
            }
#pragma unroll
            for (int mt = 0; mt < 2; mt++)
#pragma unroll
                for (int nt = 0; nt < 8; nt++)
                    mma_tf32(c[mt][nt], afr[mt], bfr[nt]);
        }
        __syncthreads();
        if (t + 2 < KCT) issue(t + 2);
    }

#pragma unroll
    for (int nt = 0; nt < 8; nt++) {
#pragma unroll
        for (int e = 0; e < 2; e++) {
            int col = bn0 + wn * 64 + nt * 8 + tg * 2 + e;
            if (col >= N) continue;
            float pb  = bias[col];
            float pb2 = (MODE == 1) ? bias2[col] : 0.f;
            float prm = 0.f, psc = 0.f, pbe = 0.f;
            if (MODE == 2) {
                prm = rm[col];
                psc = gam[col] * rsqrtf(rv[col] + EPSV);
                pbe = bet[col];
            }
#pragma unroll
            for (int mt = 0; mt < 2; mt++)
#pragma unroll
                for (int h = 0; h < 2; h++) {
                    int row = bm0 + wm * 32 + mt * 16 + gid + h * 8;
                    float v = c[mt][nt][h * 2 + e] + pb;
                    if (MODE == 1) v = tanhf(v + pb2);
                    if (MODE == 2) v = (v - prm) * psc + pbe;
                    C[(long)row * N + col] = rndtf(v);
                }
        }
    }
}

// ============ decode GEMM: 64x64x32 tile (high CTA count, low latency) ======
// Same design; 8 warps = 4(m) x 2(n); warp tile 16x32. M % 64 == 0.
template<int MODE, int DUAL>
__global__ void __launch_bounds__(256, 2) dgemm_k(
    const float* __restrict__ A,  const float* __restrict__ W,  int K,
    const float* __restrict__ A2, const float* __restrict__ W2,
    const float* __restrict__ bias, const float* __restrict__ bias2,
    const float* __restrict__ gam, const float* __restrict__ rm,
    const float* __restrict__ rv,  const float* __restrict__ bet,
    float* __restrict__ C, int M, int N)
{
    extern __shared__ uint32_t smw[];   // 3 stages x (A 2048 + B 2048) words

    const int tid  = threadIdx.x;
    const int lane = tid & 31;
    const int warp = tid >> 5;
    const int gid  = lane >> 2;
    const int tg   = lane & 3;
    const int wm   = warp & 3;          // 4 m-warps (16 rows each)
    const int wn   = warp >> 2;         // 2 n-warps (32 cols each)
    const int bm0  = blockIdx.y * 64;
    const int bn0  = blockIdx.x * 64;
    const int swz  = gid << 2;

    const int KC1 = (K + 31) >> 5;
    const int KCT = DUAL ? 2 * KC1 : KC1;

    long boff[2];
    uint32_t dA[2];
    int arow[2], akq[2];
    bool bvalid[2];
    const uint32_t smem0 = (uint32_t)__cvta_generic_to_shared(smw);
#pragma unroll
    for (int i = 0; i < 2; i++) {
        int idx = tid + i * 256;
        arow[i] = idx >> 3;             // 0..63
        akq[i]  = (idx & 7) * 4;
        int gn = bn0 + arow[i];
        bvalid[i] = gn < N;
        boff[i] = (long)(bvalid[i] ? gn : 0) * K + akq[i];
        dA[i] = smem0 +
                (uint32_t)(arow[i] * 32 + (akq[i] ^ ((arow[i] & 7) << 2))) * 4;
    }

    auto issue = [&](int t) {
        uint32_t sb = (uint32_t)(t % 3) * 16384u;
        const float* Ap; const float* Wp; int k0;
        if (!DUAL || t < KC1) { Ap = A;  Wp = W;  k0 = t << 5; }
        else                  { Ap = A2; Wp = W2; k0 = (t - KC1) << 5; }
#pragma unroll
        for (int i = 0; i < 2; i++) {
            int sz = (k0 + akq[i] + 3 < K) ? 16 : 0;
            cpa16(dA[i] + sb,
                  Ap + (long)(bm0 + arow[i]) * K + akq[i] + k0, sz);
            cpa16(dA[i] + sb + 8192u, Wp + boff[i] + k0, bvalid[i] ? sz : 0);
        }
        asm volatile("cp.async.commit_group;");
    };

    float c[4][4];
#pragma unroll
    for (int j = 0; j < 4; j++)
#pragma unroll
        for (int r = 0; r < 4; r++) c[j][r] = 0.f;

    issue(0);
    issue(1);

    for (int t = 0; t < KCT; t++) {
        if (t == KCT - 1) asm volatile("cp.async.wait_group 0;");
        else              asm volatile("cp.async.wait_group 1;");
        __syncthreads();
        const uint32_t* Asb = smw + (t % 3) * 4096;
        const uint32_t* Bsb = Asb + 2048;
#pragma unroll
        for (int kt = 0; kt < 4; kt++) {
            const int klo = ((kt << 3) + tg) ^ swz;
            const int khi = klo ^ 4;
            uint32_t afr[4];
            {
                int mrow = (wm * 16 + gid) << 5;
                afr[0] = Asb[mrow + klo];
                afr[1] = Asb[mrow + 256 + klo];
                afr[2] = Asb[mrow + khi];
                afr[3] = Asb[mrow + 256 + khi];
            }
#pragma unroll
            for (int nt = 0; nt < 4; nt++) {
                int nrow = (wn * 32 + nt * 8 + gid) << 5;
                uint32_t bfr[2];
                bfr[0] = Bsb[nrow + klo];
                bfr[1] = Bsb[nrow + khi];
                mma_tf32(c[nt], afr, bfr);
            }
        }
        __syncthreads();
        if (t + 2 < KCT) issue(t + 2);
    }

#pragma unroll
    for (int nt = 0; nt < 4; nt++) {
#pragma unroll
        for (int e = 0; e < 2; e++) {
            int col = bn0 + wn * 32 + nt * 8 + tg * 2 + e;
            if (col >= N) continue;
            float pb  = bias[col];
            float pb2 = (MODE == 1) ? bias2[col] : 0.f;
            float prm = 0.f, psc = 0.f, pbe = 0.f;
            if (MODE == 2) {
                prm = rm[col];
                psc = gam[col] * rsqrtf(rv[col] + EPSV);
                pbe = bet[col];
            }
#pragma unroll
            for (int h = 0; h < 2; h++) {
                int row = bm0 + wm * 16 + gid + h * 8;
                float v = c[nt][h * 2 + e] + pb;
                if (MODE == 1) v = tanhf(v + pb2);
                if (MODE == 2) v = (v - prm) * psc + pbe;
                C[(long)row * N + col] = rndtf(v);
            }
        }
    }
}

// ============== persistent TENSOR-CORE RNN scan =============================
__global__ void __launch_bounds__(256) scan_k(const float* __restrict__ prex,
                                              const float* __restrict__ whh,
                                              const float* __restrict__ b_hh,
                                              float* __restrict__ hs)
{
    extern __shared__ uint32_t sm[];
    uint32_t* Wt  = sm;            // 32*512 words = 64 KB
    uint32_t* Ad  = sm + 16384;    // 2 x 64x32 words = 16 KB

    const int tid  = threadIdx.x;
    const int lane = tid & 31;
    const int warp = tid >> 5;
    const int gid  = lane >> 2;
    const int tg   = lane & 3;
    const int wm   = warp & 3;
    const int wn   = warp >> 2;
    const int nb   = blockIdx.x & 15;
    const int mb   = blockIdx.x >> 4;
    const int n0   = nb * 32;
    const int m0   = mb * 64;
    const int swz  = gid << 2;

    for (int idx = tid; idx < 32 * 512; idx += 256) {
        int n = idx >> 9, k = idx & 511;
        Wt[n * 512 + (k & ~31) + ((k & 31) ^ ((n & 7) << 2))] =
            __float_as_uint(whh[(n0 + n) * FEAT + k]);
    }

    const uint32_t smemA = (uint32_t)__cvta_generic_to_shared(Ad);
    uint32_t dA[2];
    int arow[2], akq[2];
#pragma unroll
    for (int i = 0; i < 2; i++) {
        int idx = tid + i * 256;
        arow[i] = idx >> 3;
        akq[i]  = (idx & 7) * 4;
        dA[i] = smemA + (uint32_t)(arow[i] * 32 + (akq[i] ^ ((arow[i] & 7) << 2))) * 4;
    }
    __syncthreads();

    int tgt = 0;
    for (int s = 0; s < TT; s++) {
        float c[2][4];
#pragma unroll
        for (int j = 0; j < 2; j++)
#pragma unroll
            for (int r = 0; r < 4; r++) c[j][r] = 0.f;

        if (s > 0) {
            const float* hp = hs + (size_t)(s - 1) * BSZ * FEAT;
            auto issueA = [&](int ch) {
                uint32_t sb = (uint32_t)(ch & 1) * 8192u;
#pragma unroll
                for (int i = 0; i < 2; i++)
                    cpa16(dA[i] + sb,
                          hp + (m0 + arow[i]) * FEAT + ch * 32 + akq[i], 16);
                asm volatile("cp.async.commit_group;");
            };
            issueA(0);
            issueA(1);
            for (int ch = 0; ch < 16; ch++) {
                if (ch == 15) asm volatile("cp.async.wait_group 0;");
                else          asm volatile("cp.async.wait_group 1;");
                __syncthreads();
                const uint32_t* Asb = Ad + (ch & 1) * 2048;
                const uint32_t* Wc  = Wt + ch * 32;
#pragma unroll
                for (int kt = 0; kt < 4; kt++) {
                    const int klo = ((kt << 3) + tg) ^ swz;
                    const int khi = klo ^ 4;
                    uint32_t afr[4];
                    int mrow = (wm * 16 + gid) << 5;
                    afr[0] = Asb[mrow + klo];
                    afr[1] = Asb[mrow + 256 + klo];
                    afr[2] = Asb[mrow + khi];
                    afr[3] = Asb[mrow + 256 + khi];
#pragma unroll
                    for (int nt = 0; nt < 2; nt++) {
                        int nrow = (wn * 16 + nt * 8 + gid) << 9;
                        uint32_t bfr[2];
                        bfr[0] = Wc[nrow + klo];
                        bfr[1] = Wc[nrow + khi];
                        mma_tf32(c[nt], afr, bfr);
                    }
                }
                __syncthreads();
                if (ch + 2 < 16) issueA(ch + 2);
            }
        }
        const float* px = prex + (size_t)s * BSZ * FEAT;
        float*       ho = hs   + (size_t)s * BSZ * FEAT;
#pragma unroll
        for (int nt = 0; nt < 2; nt++) {
            int col = n0 + wn * 16 + nt * 8 + tg * 2;
            float b0 = b_hh[col], b1 = b_hh[col + 1];
#pragma unroll
            for (int h = 0; h < 2; h++) {
                int row = m0 + wm * 16 + gid + h * 8;
                const float2 p = *reinterpret_cast<const float2*>(
                    px + (size_t)row * FEAT + col);
                float2 o;
                o.x = rndtf(tanhf(c[nt][h * 2 + 0] + p.x + b0));
                o.y = rndtf(tanhf(c[nt][h * 2 + 1] + p.y + b1));
                *reinterpret_cast<float2*>(ho + (size_t)row * FEAT + col) = o;
            }
        }
        tgt += SCAN_GRID;
        __syncthreads();
        if (tid == 0) {
            __threadfence();
            atomicAdd(&g_bar, 1);
            while (*(volatile int*)&g_bar < tgt) __nanosleep(64);
            __threadfence();
        }
        __syncthreads();
    }
}

// ----------------------------- misc kernels --------------------------------
__global__ void zero_k() { g_loss[0] = 0.0; g_loss[1] = 0.0; g_bar = 0; }

__global__ void round_k(const float* __restrict__ src, float* __restrict__ dst,
                        int n)
{
    for (int i = blockIdx.x * blockDim.x + threadIdx.x; i < n;
         i += gridDim.x * blockDim.x)
        dst[i] = rndtf(src[i]);
}

__global__ void loss1_k(const float* __restrict__ y, const float* __restrict__ x)
{
    __shared__ double sm[256];
    const int total = (TT - 1) * BSZ * FEAT;
    double s = 0.0;
    for (int idx = blockIdx.x * blockDim.x + threadIdx.x; idx < total;
         idx += gridDim.x * blockDim.x) {
        int f = idx & (FEAT - 1);
        int b = (idx >> 9) & (BSZ - 1);
        int t = idx >> 18;
        float d = y[idx] - x[(b * TTOT + t + 1) * FEAT + f];
        s += (double)d * (double)d;
    }
    sm[threadIdx.x] = s;
    __syncthreads();
    for (int o = 128; o > 0; o >>= 1) {
        if (threadIdx.x < o) sm[threadIdx.x] += sm[threadIdx.x + o];
        __syncthreads();
    }
    if (threadIdx.x == 0) atomicAdd(&g_loss[0], sm[0]);
}

__global__ void gather_k(const float* __restrict__ xall, const int* __restrict__ tt,
                         const float* __restrict__ x, float* __restrict__ out)
{
    __shared__ double sm[256];
    int idx = blockIdx.x * blockDim.x + threadIdx.x;
    int b = idx >> 9, f = idx & (FEAT - 1);
    int g = tt[b] - 1;
    float v = xall[(g * BSZ + b) * FEAT + f];
    out[idx] = v;
    float d = v - x[(b * TTOT + TTOT - 1) * FEAT + f];
    sm[threadIdx.x] = (double)d * (double)d;
    __syncthreads();
    for (int o = 128; o > 0; o >>= 1) {
        if (threadIdx.x < o) sm[threadIdx.x] += sm[threadIdx.x + o];
        __syncthreads();
    }
    if (threadIdx.x == 0) atomicAdd(&g_loss[1], sm[0]);
}

__global__ void fin_k(float* __restrict__ out)
{
    const double n1 = (double)(TT - 1) * BSZ * FEAT;
    const double n2 = (double)BSZ * FEAT;
    out[BSZ * FEAT] = (float)(g_loss[0] / (n1 * n1) + g_loss[1] / (n2 * n2));
}

// --------------------------- host orchestration ----------------------------
#define TG_SMEM 98304
#define DG_SMEM 49152
#define SC_SMEM 81920

template<int MODE>
static void runtg(const float* A, const float* W, int K, const float* bias,
                  const float* gam, const float* rm,
                  const float* rv, const float* bet, float* C,
                  int M, int N, int rowDiv, int rowS1, int rowS2)
{
    dim3 grid((N + 127) / 128, M / 128);
    tgemm_k<MODE, 0><<<grid, 256, TG_SMEM>>>(A, W, K, nullptr, nullptr,
                                             bias, nullptr, gam, rm, rv, bet,
                                             C, M, N, rowDiv, rowS1, rowS2);
}

template<int MODE>
static void rundg(const float* A, const float* W, int K, const float* bias,
                  const float* gam, const float* rm,
                  const float* rv, const float* bet, float* C, int M, int N)
{
    dim3 grid((N + 63) / 64, M / 64);
    dgemm_k<MODE, 0><<<grid, 256, DG_SMEM>>>(A, W, K, nullptr, nullptr,
                                             bias, nullptr, gam, rm, rv, bet,
                                             C, M, N);
}

extern "C" void kernel_launch(void* const* d_in, const int* in_sizes, int n_in,
                              void* d_out, int out_size)
{
    const float* x    = (const float*)d_in[0];
    const int*   tt   = (const int*)  d_in[1];
    const float* W_ih = (const float*)d_in[2];
    const float* W_hh = (const float*)d_in[3];
    const float* b_ih = (const float*)d_in[4];
    const float* b_hh = (const float*)d_in[5];
    const float* W1   = (const float*)d_in[6];
    const float* b1   = (const float*)d_in[7];
    const float* g1   = (const float*)d_in[8];
    const float* be1  = (const float*)d_in[9];
    const float* rm1  = (const float*)d_in[10];
    const float* rv1  = (const float*)d_in[11];
    const float* W2   = (const float*)d_in[12];
    const float* b2   = (const float*)d_in[13];
    const float* g2   = (const float*)d_in[14];
    const float* be2  = (const float*)d_in[15];
    const float* rm2  = (const float*)d_in[16];
    const float* rv2  = (const float*)d_in[17];
    const float* W3   = (const float*)d_in[18];
    const float* b3   = (const float*)d_in[19];
    const float* g3   = (const float*)d_in[20];
    const float* be3  = (const float*)d_in[21];
    const float* rm3  = (const float*)d_in[22];
    const float* rv3  = (const float*)d_in[23];
    float* out = (float*)d_out;

    float *prex, *hs, *z1, *z2, *y, *xall, *hA, *hB, *z1d, *z2d;
    float *xr, *wih, *whh, *w1, *w2, *w3;
    cudaGetSymbolAddress((void**)&prex, g_prex);
    cudaGetSymbolAddress((void**)&hs,   g_hs);
    cudaGetSymbolAddress((void**)&z1,   g_z1);
    cudaGetSymbolAddress((void**)&z2,   g_z2);
    cudaGetSymbolAddress((void**)&y,    g_y);
    cudaGetSymbolAddress((void**)&xall, g_xall);
    cudaGetSymbolAddress((void**)&hA,   g_hA);
    cudaGetSymbolAddress((void**)&hB,   g_hB);
    cudaGetSymbolAddress((void**)&z1d,  g_z1d);
    cudaGetSymbolAddress((void**)&z2d,  g_z2d);
    cudaGetSymbolAddress((void**)&xr,   g_xr);
    cudaGetSymbolAddress((void**)&wih,  g_wih);
    cudaGetSymbolAddress((void**)&whh,  g_whh);
    cudaGetSymbolAddress((void**)&w1,   g_w1);
    cudaGetSymbolAddress((void**)&w2,   g_w2);
    cudaGetSymbolAddress((void**)&w3,   g_w3);

    const int BF   = BSZ * FEAT;
    const int BIGM = TT * BSZ;

    cudaFuncSetAttribute(scan_k, cudaFuncAttributeMaxDynamicSharedMemorySize,
                         SC_SMEM);
    cudaFuncSetAttribute(tgemm_k<0, 0>,
                         cudaFuncAttributeMaxDynamicSharedMemorySize, TG_SMEM);
    cudaFuncSetAttribute(tgemm_k<2, 0>,
                         cudaFuncAttributeMaxDynamicSharedMemorySize, TG_SMEM);
    cudaFuncSetAttribute(dgemm_k<1, 1>,
                         cudaFuncAttributeMaxDynamicSharedMemorySize, DG_SMEM);
    cudaFuncSetAttribute(dgemm_k<2, 0>,
                         cudaFuncAttributeMaxDynamicSharedMemorySize, DG_SMEM);

    zero_k<<<1, 1>>>();

    // 0. pre-round GEMM inputs to tf32 (rna) once
    round_k<<<2048, 256>>>(x,    xr,  TTOT * BSZ * FEAT);
    round_k<<<256,  256>>>(W_ih, wih, FEAT * FEAT);
    round_k<<<256,  256>>>(W_hh, whh, FEAT * FEAT);
    round_k<<<512,  256>>>(W1,   w1,  HID * FEAT);
    round_k<<<1024, 256>>>(W2,   w2,  HID * HID);
    round_k<<<512,  256>>>(W3,   w3,  FEAT * HID);

    // 1. prex = x @ W_ih^T + b_ih
    runtg<0>(xr, wih, FEAT, b_ih, nullptr, nullptr, nullptr, nullptr,
             prex, BIGM, FEAT, BSZ, FEAT, TTOT * FEAT);

    // 2. full RNN scan — persistent tensor-core kernel
    scan_k<<<SCAN_GRID, 256, SC_SMEM>>>(prex, whh, b_hh, hs);

    // 3. autoencoder over all 32768 rows (128x128 tiles)
    runtg<2>(hs, w1, FEAT, b1, g1, rm1, rv1, be1, z1, BIGM, HID,
             NOROW, 0, FEAT);
    runtg<2>(z1, w2, HID, b2, g2, rm2, rv2, be2, z2, BIGM, HID,
             NOROW, 0, HID);
    runtg<2>(z2, w3, HID, b3, g3, rm3, rv3, be3, y, BIGM, FEAT,
             NOROW, 0, HID);

    // 4. loss1
    loss1_k<<<2048, 256>>>(y, x);

    // 5. decode: 16 serial iterations, 4 small-tile tensor GEMMs each
    const float* hprev = hs + (TT - 1) * BF;
    const float* xprev = y  + (TT - 1) * BF;
    for (int g = 0; g < GAPS; g++) {
        float* hcur = (g & 1) ? hB : hA;
        float* xcur = xall + g * BF;
        // h2 = tanh(x_hat@W_ih^T + h@W_hh^T + b_ih + b_hh) — dual-K GEMM
        dgemm_k<1, 1><<<dim3(FEAT / 64, BSZ / 64), 256, DG_SMEM>>>(
            xprev, wih, FEAT, hprev, whh,
            b_ih, b_hh, nullptr, nullptr, nullptr, nullptr,
            hcur, BSZ, FEAT);
        rundg<2>(hcur, w1, FEAT, b1, g1, rm1, rv1, be1, z1d, BSZ, HID);
        rundg<2>(z1d, w2, HID, b2, g2, rm2, rv2, be2, z2d, BSZ, HID);
        rundg<2>(z2d, w3, HID, b3, g3, rm3, rv3, be3, xcur, BSZ, FEAT);
        hprev = hcur;
        xprev = xcur;
    }

    // 6. gather x_pred + loss2, finalize scalar loss
    gather_k<<<BF / 256, 256>>>(xall, tt, x, out);
    if (out_size > BSZ * FEAT) fin_k<<<1, 1>>>(out);
}

// round 15
// speedup vs baseline: 4.1731x; 1.0291x over previous
#include <cuda_runtime.h>
#include <cuda_bf16.h>
#include <math.h>
#include <stdint.h>

// Problem constants
#define BSZ   512
#define TT    64          // used timesteps (T_TOTAL-1)
#define TTOT  65
#define FEAT  512
#define HID   1000
#define GAPS  16
#define EPSV  1e-5f
#define SCAN_GRID 128
#define NOROW (1 << 30)

// ---------------- scratch (device globals; allocation-free) ----------------
__device__ float g_prex[TT * BSZ * FEAT];
__device__ float g_hs  [TT * BSZ * FEAT];
__device__ float g_z1  [TT * BSZ * HID];
__device__ float g_z2  [TT * BSZ * HID];
__device__ float g_y   [TT * BSZ * FEAT];
__device__ float g_xall[GAPS * BSZ * FEAT];
__device__ float g_hA  [BSZ * FEAT];
__device__ float g_hB  [BSZ * FEAT];
__device__ float g_z1d [BSZ * HID];
__device__ float g_z2d [BSZ * HID];
// tf32-pre-rounded copies
__device__ float g_xr  [TTOT * BSZ * FEAT];
__device__ float g_wih [FEAT * FEAT];
__device__ float g_whh [FEAT * FEAT];
__device__ float g_w1  [HID * FEAT];
__device__ float g_w2  [HID * HID];
__device__ float g_w3  [FEAT * HID];
__device__ double g_loss[2];
__device__ int    g_bar;

// ---------------- tf32 helpers ----------------
__device__ __forceinline__ uint32_t f2tf(float f) {
    uint32_t u;
    asm("cvt.rna.tf32.f32 %0, %1;" : "=r"(u) : "f"(f));
    return u;
}
__device__ __forceinline__ float rndtf(float f) { return __uint_as_float(f2tf(f)); }

__device__ __forceinline__ void mma_tf32(float* c, const uint32_t* a,
                                         const uint32_t* b) {
    asm volatile(
        "mma.sync.aligned.m16n8k8.row.col.f32.tf32.tf32.f32 "
        "{%0,%1,%2,%3}, {%4,%5,%6,%7}, {%8,%9}, {%0,%1,%2,%3};"
        : "+f"(c[0]), "+f"(c[1]), "+f"(c[2]), "+f"(c[3])
        : "r"(a[0]), "r"(a[1]), "r"(a[2]), "r"(a[3]), "r"(b[0]), "r"(b[1]));
}
__device__ __forceinline__ void cpa16(uint32_t dst, const float* src, int sz) {
    asm volatile("cp.async.cg.shared.global [%0], [%1], 16, %2;"
                 :: "r"(dst), "l"(src), "r"(sz));
}

// ============ tf32 tensor GEMM, cp.async 3-stage, 128x128 tile ==============
// C = ep( A@W^T [+ A2@W2^T, same K] + bias )
// 8 warps = 4(m) x 2(n); warp tile 32x64. Inputs tf32-rounded; M % 128 == 0.
// MODE 0: acc+bias
// MODE 1: tanh(acc+bias+bias2)     (DUAL=1 cell)
// MODE 2: BN epilogue
// MODE 3: BN epilogue + loss1 accumulation vs x (passed as A2; time-major C)
template<int MODE, int DUAL>
__global__ void __launch_bounds__(256, 2) tgemm_k(
    const float* __restrict__ A,  const float* __restrict__ W,  int K,
    const float* __restrict__ A2, const float* __restrict__ W2,
    const float* __restrict__ bias, const float* __restrict__ bias2,
    const float* __restrict__ gam, const float* __restrict__ rm,
    const float* __restrict__ rv,  const float* __restrict__ bet,
    float* __restrict__ C, int M, int N,
    int rowDiv, int rowS1, int rowS2)
{
    extern __shared__ uint32_t smw[];   // 3 stages x (A 4096 + B 4096) words

    const int tid  = threadIdx.x;
    const int lane = tid & 31;
    const int warp = tid >> 5;
    const int gid  = lane >> 2;
    const int tg   = lane & 3;
    const int wm   = warp & 3;
    const int wn   = warp >> 2;
    const int bm0  = blockIdx.y * 128;
    const int bn0  = blockIdx.x * 128;
    const int swz  = gid << 2;

    const int KC1 = (K + 31) >> 5;
    const int KCT = DUAL ? 2 * KC1 : KC1;

    long aoff0[4], boff[4];
    uint32_t dA[4];
    bool bvalid[4];
    const uint32_t smem0 = (uint32_t)__cvta_generic_to_shared(smw);
#pragma unroll
    for (int i = 0; i < 4; i++) {
        int idx = tid + i * 256;
        int r   = idx >> 3;
        int kq  = (idx & 7) * 4;
        int gm  = bm0 + r;
        aoff0[i] = (long)(gm / rowDiv) * rowS1 + (long)(gm % rowDiv) * rowS2 + kq;
        int gn = bn0 + r;
        bvalid[i] = gn < N;
        boff[i] = (long)(bvalid[i] ? gn : 0) * K + kq;
        dA[i] = smem0 + (uint32_t)(r * 32 + (kq ^ ((r & 7) << 2))) * 4;
    }

    auto issue = [&](int t) {
        uint32_t sb = (uint32_t)(t % 3) * 32768u;
        const float* Ap; const float* Wp; int k0; bool p0;
        if (!DUAL || t < KC1) { Ap = A;  Wp = W;  k0 = t << 5;         p0 = true; }
        else                  { Ap = A2; Wp = W2; k0 = (t - KC1) << 5; p0 = false; }
#pragma unroll
        for (int i = 0; i < 4; i++) {
            int idx = tid + i * 256;
            int r   = idx >> 3;
            int kq  = (idx & 7) * 4;
            int sz  = (k0 + kq + 3 < K) ? 16 : 0;
            long ao = p0 ? aoff0[i] : ((long)(bm0 + r) * K + kq);
            cpa16(dA[i] + sb,          Ap + ao + k0,      sz);
            cpa16(dA[i] + sb + 16384u, Wp + boff[i] + k0, bvalid[i] ? sz : 0);
        }
        asm volatile("cp.async.commit_group;");
    };

    float c[2][8][4];
#pragma unroll
    for (int i = 0; i < 2; i++)
#pragma unroll
        for (int j = 0; j < 8; j++)
#pragma unroll
            for (int r = 0; r < 4; r++) c[i][j][r] = 0.f;

    issue(0);
    issue(1);

    for (int t = 0; t < KCT; t++) {
        if (t == KCT - 1) asm volatile("cp.async.wait_group 0;");
        else              asm volatile("cp.async.wait_group 1;");
        __syncthreads();
        const uint32_t* Asb = smw + (t % 3) * 8192;
        const uint32_t* Bsb = Asb + 4096;
#pragma unroll
        for (int kt = 0; kt < 4; kt++) {
            const int klo = ((kt << 3) + tg) ^ swz;
            const int khi = klo ^ 4;
            uint32_t bfr[8][2];
#pragma unroll
            for (int nt = 0; nt < 8; nt++) {
                int nrow = (wn * 64 + nt * 8 + gid) << 5;
                bfr[nt][0] = Bsb[nrow + klo];
                bfr[nt][1] = Bsb[nrow + khi];
            }
            uint32_t afr[2][4];
#pragma unroll
            for (int mt = 0; mt < 2; mt++) {
                int mrow = (wm * 32 + mt * 16 + gid) << 5;
                afr[mt][0] = Asb[mrow + klo];
                afr[mt][1] = Asb[mrow + 256 + klo];
                afr[mt][2] = Asb[mrow + khi];
                afr[mt][3] = Asb[mrow + 256 + khi];
            }
#pragma unroll
            for (int mt = 0; mt < 2; mt++)
#pragma unroll
                for (int nt = 0; nt < 8; nt++)
                    mma_tf32(c[mt][nt], afr[mt], bfr[nt]);
        }
        __syncthreads();
        if (t + 2 < KCT) issue(t + 2);
    }

    float lacc = 0.f;   // MODE 3 loss partial
#pragma unroll
    for (int nt = 0; nt < 8; nt++) {
#pragma unroll
        for (int e = 0; e < 2; e++) {
            int col = bn0 + wn * 64 + nt * 8 + tg * 2 + e;
            if (col >= N) continue;
            float pb  = bias[col];
            float pb2 = (MODE == 1) ? bias2[col] : 0.f;
            float prm = 0.f, psc = 0.f, pbe = 0.f;
            if (MODE >= 2) {
                prm = rm[col];
                psc = gam[col] * rsqrtf(rv[col] + EPSV);
                pbe = bet[col];
            }
#pragma unroll
            for (int mt = 0; mt < 2; mt++)
#pragma unroll
                for (int h = 0; h < 2; h++) {
                    int row = bm0 + wm * 32 + mt * 16 + gid + h * 8;
                    float v = c[mt][nt][h * 2 + e] + pb;
                    if (MODE == 1) v = tanhf(v + pb2);
                    if (MODE >= 2) v = (v - prm) * psc + pbe;
                    float w = rndtf(v);
                    C[(long)row * N + col] = w;
                    if (MODE == 3 && row < (TT - 1) * BSZ) {
                        // y[t*B+b, col] vs x[b, t+1, col]
                        int tt2 = row >> 9, b = row & (BSZ - 1);
                        float d = w - A2[((long)b * TTOT + tt2 + 1) * FEAT + col];
                        lacc = fmaf(d, d, lacc);
                    }
                }
        }
    }
    if (MODE == 3) {
        __syncthreads();                 // smem stages no longer needed
        double* rd = (double*)smw;
        rd[tid] = (double)lacc;
        __syncthreads();
        for (int o = 128; o > 0; o >>= 1) {
            if (tid < o) rd[tid] += rd[tid + o];
            __syncthreads();
        }
        if (tid == 0) atomicAdd(&g_loss[0], rd[0]);
    }
}

// ============ decode GEMM: 64x64x32 tile (high CTA count, low latency) ======
template<int MODE, int DUAL>
__global__ void __launch_bounds__(256, 2) dgemm_k(
    const float* __restrict__ A,  const float* __restrict__ W,  int K,
    const float* __restrict__ A2, const float* __restrict__ W2,
    const float* __restrict__ bias, const float* __restrict__ bias2,
    const float* __restrict__ gam, const float* __restrict__ rm,
    const float* __restrict__ rv,  const float* __restrict__ bet,
    float* __restrict__ C, int M, int N)
{
    extern __shared__ uint32_t smw[];   // 3 stages x (A 2048 + B 2048) words

    const int tid  = threadIdx.x;
    const int lane = tid & 31;
    const int warp = tid >> 5;
    const int gid  = lane >> 2;
    const int tg   = lane & 3;
    const int wm   = warp & 3;
    const int wn   = warp >> 2;
    const int bm0  = blockIdx.y * 64;
    const int bn0  = blockIdx.x * 64;
    const int swz  = gid << 2;

    const int KC1 = (K + 31) >> 5;
    const int KCT = DUAL ? 2 * KC1 : KC1;

    long boff[2];
    uint32_t dA[2];
    int arow[2], akq[2];
    bool bvalid[2];
    const uint32_t smem0 = (uint32_t)__cvta_generic_to_shared(smw);
#pragma unroll
    for (int i = 0; i < 2; i++) {
        int idx = tid + i * 256;
        arow[i] = idx >> 3;
        akq[i]  = (idx & 7) * 4;
        int gn = bn0 + arow[i];
        bvalid[i] = gn < N;
        boff[i] = (long)(bvalid[i] ? gn : 0) * K + akq[i];
        dA[i] = smem0 +
                (uint32_t)(arow[i] * 32 + (akq[i] ^ ((arow[i] & 7) << 2))) * 4;
    }

    auto issue = [&](int t) {
        uint32_t sb = (uint32_t)(t % 3) * 16384u;
        const float* Ap; const float* Wp; int k0;
        if (!DUAL || t < KC1) { Ap = A;  Wp = W;  k0 = t << 5; }
        else                  { Ap = A2; Wp = W2; k0 = (t - KC1) << 5; }
#pragma unroll
        for (int i = 0; i < 2; i++) {
            int sz = (k0 + akq[i] + 3 < K) ? 16 : 0;
            cpa16(dA[i] + sb,
                  Ap + (long)(bm0 + arow[i]) * K + akq[i] + k0, sz);
            cpa16(dA[i] + sb + 8192u, Wp + boff[i] + k0, bvalid[i] ? sz : 0);
        }
        asm volatile("cp.async.commit_group;");
    };

    float c[4][4];
#pragma unroll
    for (int j = 0; j < 4; j++)
#pragma unroll
        for (int r = 0; r < 4; r++) c[j][r] = 0.f;

    issue(0);
    issue(1);

    for (int t = 0; t < KCT; t++) {
        if (t == KCT - 1) asm volatile("cp.async.wait_group 0;");
        else              asm volatile("cp.async.wait_group 1;");
        __syncthreads();
        const uint32_t* Asb = smw + (t % 3) * 4096;
        const uint32_t* Bsb = Asb + 2048;
#pragma unroll
        for (int kt = 0; kt < 4; kt++) {
            const int klo = ((kt << 3) + tg) ^ swz;
            const int khi = klo ^ 4;
            uint32_t afr[4];
            {
                int mrow = (wm * 16 + gid) << 5;
                afr[0] = Asb[mrow + klo];
                afr[1] = Asb[mrow + 256 + klo];
                afr[2] = Asb[mrow + khi];
                afr[3] = Asb[mrow + 256 + khi];
            }
#pragma unroll
            for (int nt = 0; nt < 4; nt++) {
                int nrow = (wn * 32 + nt * 8 + gid) << 5;
                uint32_t bfr[2];
                bfr[0] = Bsb[nrow + klo];
                bfr[1] = Bsb[nrow + khi];
                mma_tf32(c[nt], afr, bfr);
            }
        }
        __syncthreads();
        if (t + 2 < KCT) issue(t + 2);
    }

#pragma unroll
    for (int nt = 0; nt < 4; nt++) {
#pragma unroll
        for (int e = 0; e < 2; e++) {
            int col = bn0 + wn * 32 + nt * 8 + tg * 2 + e;
            if (col >= N) continue;
            float pb  = bias[col];
            float pb2 = (MODE == 1) ? bias2[col] : 0.f;
            float prm = 0.f, psc = 0.f, pbe = 0.f;
            if (MODE == 2) {
                prm = rm[col];
                psc = gam[col] * rsqrtf(rv[col] + EPSV);
                pbe = bet[col];
            }
#pragma unroll
            for (int h = 0; h < 2; h++) {
                int row = bm0 + wm * 16 + gid + h * 8;
                float v = c[nt][h * 2 + e] + pb;
                if (MODE == 1) v = tanhf(v + pb2);
                if (MODE == 2) v = (v - prm) * psc + pbe;
                C[(long)row * N + col] = rndtf(v);
            }
        }
    }
}

// ============== persistent TENSOR-CORE RNN scan =============================
__global__ void __launch_bounds__(256) scan_k(const float* __restrict__ prex,
                                              const float* __restrict__ whh,
                                              const float* __restrict__ b_hh,
                                              float* __restrict__ hs)
{
    extern __shared__ uint32_t sm[];
    uint32_t* Wt  = sm;            // 32*512 words = 64 KB
    uint32_t* Ad  = sm + 16384;    // 2 x 64x32 words = 16 KB

    const int tid  = threadIdx.x;
    const int lane = tid & 31;
    const int warp = tid >> 5;
    const int gid  = lane >> 2;
    const int tg   = lane & 3;
    const int wm   = warp & 3;
    const int wn   = warp >> 2;
    const int nb   = blockIdx.x & 15;
    const int mb   = blockIdx.x >> 4;
    const int n0   = nb * 32;
    const int m0   = mb * 64;
    const int swz  = gid << 2;

    for (int idx = tid; idx < 32 * 512; idx += 256) {
        int n = idx >> 9, k = idx & 511;
        Wt[n * 512 + (k & ~31) + ((k & 31) ^ ((n & 7) << 2))] =
            __float_as_uint(whh[(n0 + n) * FEAT + k]);
    }

    const uint32_t smemA = (uint32_t)__cvta_generic_to_shared(Ad);
    uint32_t dA[2];
    int arow[2], akq[2];
#pragma unroll
    for (int i = 0; i < 2; i++) {
        int idx = tid + i * 256;
        arow[i] = idx >> 3;
        akq[i]  = (idx & 7) * 4;
        dA[i] = smemA + (uint32_t)(arow[i] * 32 + (akq[i] ^ ((arow[i] & 7) << 2))) * 4;
    }
    __syncthreads();

    int tgt = 0;
    for (int s = 0; s < TT; s++) {
        float c[2][4];
#pragma unroll
        for (int j = 0; j < 2; j++)
#pragma unroll
            for (int r = 0; r < 4; r++) c[j][r] = 0.f;

        if (s > 0) {
            const float* hp = hs + (size_t)(s - 1) * BSZ * FEAT;
            auto issueA = [&](int ch) {
                uint32_t sb = (uint32_t)(ch & 1) * 8192u;
#pragma unroll
                for (int i = 0; i < 2; i++)
                    cpa16(dA[i] + sb,
                          hp + (m0 + arow[i]) * FEAT + ch * 32 + akq[i], 16);
                asm volatile("cp.async.commit_group;");
            };
            issueA(0);
            issueA(1);
            for (int ch = 0; ch < 16; ch++) {
                if (ch == 15) asm volatile("cp.async.wait_group 0;");
                else          asm volatile("cp.async.wait_group 1;");
                __syncthreads();
                const uint32_t* Asb = Ad + (ch & 1) * 2048;
                const uint32_t* Wc  = Wt + ch * 32;
#pragma unroll
                for (int kt = 0; kt < 4; kt++) {
                    const int klo = ((kt << 3) + tg) ^ swz;
                    const int khi = klo ^ 4;
                    uint32_t afr[4];
                    int mrow = (wm * 16 + gid) << 5;
                    afr[0] = Asb[mrow + klo];
                    afr[1] = Asb[mrow + 256 + klo];
                    afr[2] = Asb[mrow + khi];
                    afr[3] = Asb[mrow + 256 + khi];
#pragma unroll
                    for (int nt = 0; nt < 2; nt++) {
                        int nrow = (wn * 16 + nt * 8 + gid) << 9;
                        uint32_t bfr[2];
                        bfr[0] = Wc[nrow + klo];
                        bfr[1] = Wc[nrow + khi];
                        mma_tf32(c[nt], afr, bfr);
                    }
                }
                __syncthreads();
                if (ch + 2 < 16) issueA(ch + 2);
            }
        }
        const float* px = prex + (size_t)s * BSZ * FEAT;
        float*       ho = hs   + (size_t)s * BSZ * FEAT;
#pragma unroll
        for (int nt = 0; nt < 2; nt++) {
            int col = n0 + wn * 16 + nt * 8 + tg * 2;
            float b0 = b_hh[col], b1 = b_hh[col + 1];
#pragma unroll
            for (int h = 0; h < 2; h++) {
                int row = m0 + wm * 16 + gid + h * 8;
                const float2 p = *reinterpret_cast<const float2*>(
                    px + (size_t)row * FEAT + col);
                float2 o;
                o.x = rndtf(tanhf(c[nt][h * 2 + 0] + p.x + b0));
                o.y = rndtf(tanhf(c[nt][h * 2 + 1] + p.y + b1));
                *reinterpret_cast<float2*>(ho + (size_t)row * FEAT + col) = o;
            }
        }
        tgt += SCAN_GRID;
        __syncthreads();
        if (tid == 0) {
            __threadfence();
            atomicAdd(&g_bar, 1);
            while (*(volatile int*)&g_bar < tgt) __nanosleep(64);
            __threadfence();
        }
        __syncthreads();
    }
}

// ----------------------------- misc kernels --------------------------------
// One fused kernel: zero the accumulators + tf32-round x and all 5 weights.
__global__ void round_all_k(const float* __restrict__ x,
                            const float* __restrict__ wih_s,
                            const float* __restrict__ whh_s,
                            const float* __restrict__ w1_s,
                            const float* __restrict__ w2_s,
                            const float* __restrict__ w3_s)
{
    if (blockIdx.x == 0 && threadIdx.x == 0) {
        g_loss[0] = 0.0; g_loss[1] = 0.0; g_bar = 0;
    }
    const int N0 = TTOT * BSZ * FEAT;          // x
    const int N1 = N0 + FEAT * FEAT;           // W_ih
    const int N2 = N1 + FEAT * FEAT;           // W_hh
    const int N3 = N2 + HID * FEAT;            // W1
    const int N4 = N3 + HID * HID;             // W2
    const int N5 = N4 + FEAT * HID;            // W3
    for (int i = blockIdx.x * blockDim.x + threadIdx.x; i < N5;
         i += gridDim.x * blockDim.x) {
        if      (i < N0) g_xr [i]      = rndtf(x[i]);
        else if (i < N1) g_wih[i - N0] = rndtf(wih_s[i - N0]);
        else if (i < N2) g_whh[i - N1] = rndtf(whh_s[i - N1]);
        else if (i < N3) g_w1 [i - N2] = rndtf(w1_s[i - N2]);
        else if (i < N4) g_w2 [i - N3] = rndtf(w2_s[i - N3]);
        else             g_w3 [i - N4] = rndtf(w3_s[i - N4]);
    }
}

__global__ void gather_k(const float* __restrict__ xall, const int* __restrict__ tt,
                         const float* __restrict__ x, float* __restrict__ out)
{
    __shared__ double sm[256];
    int idx = blockIdx.x * blockDim.x + threadIdx.x;
    int b = idx >> 9, f = idx & (FEAT - 1);
    int g = tt[b] - 1;
    float v = xall[(g * BSZ + b) * FEAT + f];
    out[idx] = v;
    float d = v - x[(b * TTOT + TTOT - 1) * FEAT + f];
    sm[threadIdx.x] = (double)d * (double)d;
    __syncthreads();
    for (int o = 128; o > 0; o >>= 1) {
        if (threadIdx.x < o) sm[threadIdx.x] += sm[threadIdx.x + o];
        __syncthreads();
    }
    if (threadIdx.x == 0) atomicAdd(&g_loss[1], sm[0]);
}

__global__ void fin_k(float* __restrict__ out)
{
    const double n1 = (double)(TT - 1) * BSZ * FEAT;
    const double n2 = (double)BSZ * FEAT;
    out[BSZ * FEAT] = (float)(g_loss[0] / (n1 * n1) + g_loss[1] / (n2 * n2));
}

// --------------------------- host orchestration ----------------------------
#define TG_SMEM 98304
#define DG_SMEM 49152
#define SC_SMEM 81920

template<int MODE>
static void runtg(const float* A, const float* W, int K, const float* bias,
                  const float* gam, const float* rm,
                  const float* rv, const float* bet, float* C,
                  int M, int N, int rowDiv, int rowS1, int rowS2,
                  const float* xref = nullptr)
{
    dim3 grid((N + 127) / 128, M / 128);
    tgemm_k<MODE, 0><<<grid, 256, TG_SMEM>>>(A, W, K, xref, nullptr,
                                             bias, nullptr, gam, rm, rv, bet,
                                             C, M, N, rowDiv, rowS1, rowS2);
}

template<int MODE>
static void rundg(const float* A, const float* W, int K, const float* bias,
                  const float* gam, const float* rm,
                  const float* rv, const float* bet, float* C, int M, int N)
{
    dim3 grid((N + 63) / 64, M / 64);
    dgemm_k<MODE, 0><<<grid, 256, DG_SMEM>>>(A, W, K, nullptr, nullptr,
                                             bias, nullptr, gam, rm, rv, bet,
                                             C, M, N);
}

extern "C" void kernel_launch(void* const* d_in, const int* in_sizes, int n_in,
                              void* d_out, int out_size)
{
    const float* x    = (const float*)d_in[0];
    const int*   tt   = (const int*)  d_in[1];
    const float* W_ih = (const float*)d_in[2];
    const float* W_hh = (const float*)d_in[3];
    const float* b_ih = (const float*)d_in[4];
    const float* b_hh = (const float*)d_in[5];
    const float* W1   = (const float*)d_in[6];
    const float* b1   = (const float*)d_in[7];
    const float* g1   = (const float*)d_in[8];
    const float* be1  = (const float*)d_in[9];
    const float* rm1  = (const float*)d_in[10];
    const float* rv1  = (const float*)d_in[11];
    const float* W2   = (const float*)d_in[12];
    const float* b2   = (const float*)d_in[13];
    const float* g2   = (const float*)d_in[14];
    const float* be2  = (const float*)d_in[15];
    const float* rm2  = (const float*)d_in[16];
    const float* rv2  = (const float*)d_in[17];
    const float* W3   = (const float*)d_in[18];
    const float* b3   = (const float*)d_in[19];
    const float* g3   = (const float*)d_in[20];
    const float* be3  = (const float*)d_in[21];
    const float* rm3  = (const float*)d_in[22];
    const float* rv3  = (const float*)d_in[23];
    float* out = (float*)d_out;

    float *prex, *hs, *z1, *z2, *y, *xall, *hA, *hB, *z1d, *z2d;
    float *xr, *wih, *whh, *w1, *w2, *w3;
    cudaGetSymbolAddress((void**)&prex, g_prex);
    cudaGetSymbolAddress((void**)&hs,   g_hs);
    cudaGetSymbolAddress((void**)&z1,   g_z1);
    cudaGetSymbolAddress((void**)&z2,   g_z2);
    cudaGetSymbolAddress((void**)&y,    g_y);
    cudaGetSymbolAddress((void**)&xall, g_xall);
    cudaGetSymbolAddress((void**)&hA,   g_hA);
    cudaGetSymbolAddress((void**)&hB,   g_hB);
    cudaGetSymbolAddress((void**)&z1d,  g_z1d);
    cudaGetSymbolAddress((void**)&z2d,  g_z2d);
    cudaGetSymbolAddress((void**)&xr,   g_xr);
    cudaGetSymbolAddress((void**)&wih,  g_wih);
    cudaGetSymbolAddress((void**)&whh,  g_whh);
    cudaGetSymbolAddress((void**)&w1,   g_w1);
    cudaGetSymbolAddress((void**)&w2,   g_w2);
    cudaGetSymbolAddress((void**)&w3,   g_w3);

    const int BF   = BSZ * FEAT;
    const int BIGM = TT * BSZ;

    cudaFuncSetAttribute(scan_k, cudaFuncAttributeMaxDynamicSharedMemorySize,
                         SC_SMEM);
    cudaFuncSetAttribute(tgemm_k<0, 0>,
                         cudaFuncAttributeMaxDynamicSharedMemorySize, TG_SMEM);
    cudaFuncSetAttribute(tgemm_k<2, 0>,
                         cudaFuncAttributeMaxDynamicSharedMemorySize, TG_SMEM);
    cudaFuncSetAttribute(tgemm_k<3, 0>,
                         cudaFuncAttributeMaxDynamicSharedMemorySize, TG_SMEM);
    cudaFuncSetAttribute(dgemm_k<1, 1>,
                         cudaFuncAttributeMaxDynamicSharedMemorySize, DG_SMEM);
    cudaFuncSetAttribute(dgemm_k<2, 0>,
                         cudaFuncAttributeMaxDynamicSharedMemorySize, DG_SMEM);

    // 0. zero accumulators + pre-round all GEMM inputs (ONE launch)
    round_all_k<<<2048, 256>>>(x, W_ih, W_hh, W1, W2, W3);

    // 1. prex = x @ W_ih^T + b_ih                                 (launch 2)
    runtg<0>(xr, wih, FEAT, b_ih, nullptr, nullptr, nullptr, nullptr,
             prex, BIGM, FEAT, BSZ, FEAT, TTOT * FEAT);

    // 2. full RNN scan — persistent tensor-core kernel            (launch 3)
    scan_k<<<SCAN_GRID, 256, SC_SMEM>>>(prex, whh, b_hh, hs);

    // 3. autoencoder; layer 3 fuses loss1                         (4,5,6)
    runtg<2>(hs, w1, FEAT, b1, g1, rm1, rv1, be1, z1, BIGM, HID,
             NOROW, 0, FEAT);
    runtg<2>(z1, w2, HID, b2, g2, rm2, rv2, be2, z2, BIGM, HID,
             NOROW, 0, HID);
    runtg<3>(z2, w3, HID, b3, g3, rm3, rv3, be3, y, BIGM, FEAT,
             NOROW, 0, HID, x);

    // 4. decode: 16 serial iterations, 4 small-tile tensor GEMMs each
    const float* hprev = hs + (TT - 1) * BF;
    const float* xprev = y  + (TT - 1) * BF;
    for (int g = 0; g < GAPS; g++) {
        float* hcur = (g & 1) ? hB : hA;
        float* xcur = xall + g * BF;
        dgemm_k<1, 1><<<dim3(FEAT / 64, BSZ / 64), 256, DG_SMEM>>>(
            xprev, wih, FEAT, hprev, whh,
            b_ih, b_hh, nullptr, nullptr, nullptr, nullptr,
            hcur, BSZ, FEAT);
        rundg<2>(hcur, w1, FEAT, b1, g1, rm1, rv1, be1, z1d, BSZ, HID);
        rundg<2>(z1d, w2, HID, b2, g2, rm2, rv2, be2, z2d, BSZ, HID);
        rundg<2>(z2d, w3, HID, b3, g3, rm3, rv3, be3, xcur, BSZ, FEAT);
        hprev = hcur;
        xprev = xcur;
    }

    // 5. gather x_pred + loss2, finalize scalar loss
    gather_k<<<BF / 256, 256>>>(xall, tt, x, out);
    if (out_size > BSZ * FEAT) fin_k<<<1, 1>>>(out);
}